// round 7
// baseline (speedup 1.0000x reference)
#include <cuda_runtime.h>
#include <cuda_bf16.h>
#include <cstdint>

// Problem constants
#define VOCAB 10000
#define HID   256
#define BATCH 32
#define SEQL  512
#define MTOT  (SEQL * BATCH)   // 16384

typedef unsigned long long u64;

// ---------------- scratch (bf16 split operands) ----------------
__device__ __nv_bfloat16 g_yh[(size_t)MTOT * HID];    // Y hi  [M, K]
__device__ __nv_bfloat16 g_yl[(size_t)MTOT * HID];    // Y lo  [M, K]
__device__ __nv_bfloat16 g_wth[(size_t)VOCAB * HID];  // Wd^T hi [N, K]
__device__ __nv_bfloat16 g_wtl[(size_t)VOCAB * HID];  // Wd^T lo [N, K]

// ================= helpers =================
__device__ __forceinline__ uint32_t smem_u32(const void* p) {
    uint32_t a;
    asm("{ .reg .u64 t; cvta.to.shared.u64 t, %1; cvt.u32.u64 %0, t; }"
        : "=r"(a) : "l"(p));
    return a;
}
__device__ __forceinline__ void cpa16(uint32_t dst, const void* src, uint32_t sz) {
    asm volatile("cp.async.cg.shared.global [%0], [%1], 16, %2;"
                 :: "r"(dst), "l"(src), "r"(sz) : "memory");
}
__device__ __forceinline__ void ldm_x4(uint32_t* r, uint32_t addr) {
    asm volatile("ldmatrix.sync.aligned.m8n8.x4.shared.b16 {%0,%1,%2,%3}, [%4];"
                 : "=r"(r[0]), "=r"(r[1]), "=r"(r[2]), "=r"(r[3]) : "r"(addr));
}
__device__ __forceinline__ void mma_bf16(float* c, const uint32_t* a, const uint32_t* b) {
    asm volatile(
        "mma.sync.aligned.m16n8k16.row.col.f32.bf16.bf16.f32 "
        "{%0,%1,%2,%3}, {%4,%5,%6,%7}, {%8,%9}, {%0,%1,%2,%3};"
        : "+f"(c[0]), "+f"(c[1]), "+f"(c[2]), "+f"(c[3])
        : "r"(a[0]), "r"(a[1]), "r"(a[2]), "r"(a[3]), "r"(b[0]), "r"(b[1]));
}
__device__ __forceinline__ u64 packf2(float lo, float hi) {
    u64 d;
    asm("mov.b64 %0, {%1, %2};" : "=l"(d) : "f"(lo), "f"(hi));
    return d;
}
__device__ __forceinline__ void unpackf2(u64 d, float& lo, float& hi) {
    asm("mov.b64 {%0, %1}, %2;" : "=f"(lo), "=f"(hi) : "l"(d));
}
__device__ __forceinline__ u64 fma2(u64 a, u64 b, u64 c) {
    u64 d;
    asm("fma.rn.f32x2 %0, %1, %2, %3;" : "=l"(d) : "l"(a), "l"(b), "l"(c));
    return d;
}
// fast tanh: 1 - 2/(e^{2x}+1); saturates correctly at +-inf
__device__ __forceinline__ float fast_tanh(float x) {
    float z = __expf(2.0f * x);
    return 1.0f - __fdividef(2.0f, z + 1.0f);
}

// ---------------- Recurrence: 2-CTA cluster per batch, Whh in registers ----
// CTA rank r owns outputs [r*128, r*128+128). 256 threads: lane pairs split k
// (even lane k in [0,128), odd lane k in [128,256)). Each thread holds 128
// Whh column values as 64 f32x2 register pairs -> zero smem Whh traffic.
// h exchanged via DSMEM store + cluster barrier each step; double-buffered.
__global__ void __launch_bounds__(256, 1) __cluster_dims__(2, 1, 1)
rnn_kernel(const int* __restrict__ tokens, const float* __restrict__ state,
           const float* __restrict__ Wxh, const float* __restrict__ Whh,
           const float* __restrict__ bh, float* __restrict__ hfin)
{
    __shared__ __align__(16) float hbuf[2][HID];

    uint32_t rank;
    asm("mov.u32 %0, %%cluster_ctarank;" : "=r"(rank));
    const int b    = blockIdx.x >> 1;
    const int tid  = threadIdx.x;
    const int lane = tid & 31;
    const int wid  = tid >> 5;
    const int half = lane & 1;                    // k-half selector
    const int o    = (int)rank * 128 + wid * 16 + (lane >> 1);  // global output
    const int kb   = half * 128;                  // k base for this thread

    // Whh[kb + kk][o], kk in [0,128), packed as 64 f32x2
    u64 W2[64];
#pragma unroll
    for (int q = 0; q < 64; q++)
        W2[q] = packf2(Whh[(kb + 2 * q) * HID + o],
                       Whh[(kb + 2 * q + 1) * HID + o]);

    const float bias = (half == 0) ? bh[o] : 0.f;

    // init h0 (each CTA fills its full local copy)
    hbuf[0][tid] = state[b * HID + tid];

    // peer CTA's hbuf base address (DSMEM)
    uint32_t hloc = smem_u32(&hbuf[0][0]);
    uint32_t hrem;
    asm("mapa.shared::cluster.u32 %0, %1, %2;" : "=r"(hrem)
        : "r"(hloc), "r"(rank ^ 1u));

    // everything (W loads, h0) ready cluster-wide
    asm volatile("barrier.cluster.arrive.aligned;" ::: "memory");
    asm volatile("barrier.cluster.wait.aligned;"   ::: "memory");

    const int* toks = tokens + b * SEQL;
    float e = (half == 0) ? Wxh[toks[0] * HID + o] : 0.f;

    for (int t = 0; t < SEQL; t++) {
        const ulonglong2* h22 = (const ulonglong2*)(&hbuf[t & 1][kb]);

        u64 a0 = packf2(e + bias, 0.f), a1 = 0ull, a2 = 0ull, a3 = 0ull;
#pragma unroll
        for (int q = 0; q < 32; q += 2) {         // 32 ulonglong2 = 128 floats
            ulonglong2 h0 = h22[q];
            a0 = fma2(h0.x, W2[2 * q],     a0);
            a1 = fma2(h0.y, W2[2 * q + 1], a1);
            ulonglong2 h1 = h22[q + 1];
            a2 = fma2(h1.x, W2[2 * q + 2], a2);
            a3 = fma2(h1.y, W2[2 * q + 3], a3);
        }
        float s0, s1, s2, s3, s4, s5, s6, s7;
        unpackf2(a0, s0, s1); unpackf2(a1, s2, s3);
        unpackf2(a2, s4, s5); unpackf2(a3, s6, s7);
        float part = ((s0 + s2) + (s1 + s3)) + ((s4 + s6) + (s5 + s7));
        // combine k-halves: odd lane -> even lane
        part += __shfl_down_sync(0xffffffffu, part, 1);

        const int nb = (t + 1) & 1;
        float hn = 0.f;
        if (half == 0) {
            hn = fast_tanh(part);
            hbuf[nb][o] = hn;                     // local copy
            uint32_t raddr = hrem + (uint32_t)(nb * HID + o) * 4u;
            asm volatile("st.shared::cluster.f32 [%0], %1;"
                         :: "r"(raddr), "f"(hn));  // peer copy
        }
        // release: orders local + DSMEM stores cluster-wide
        asm volatile("barrier.cluster.arrive.aligned;" ::: "memory");

        // overlapped independent work (global stores + next-token prefetch)
        float e_next = 0.f;
        if (half == 0) {
            size_t oidx = ((size_t)t * BATCH + b) * HID + o;
            __nv_bfloat16 hh = __float2bfloat16(hn);
            g_yh[oidx] = hh;
            g_yl[oidx] = __float2bfloat16(hn - __bfloat162float(hh));
            if (t == SEQL - 1) hfin[b * HID + o] = hn;
            if (t + 1 < SEQL) e_next = Wxh[toks[t + 1] * HID + o];
        }

        asm volatile("barrier.cluster.wait.aligned;" ::: "memory");
        e = e_next;
    }
}

// ---------------- Wd transpose + bf16 split: [K,N] f32 -> [N,K] bf16 hi/lo --
__global__ void __launch_bounds__(256)
wd_transpose_split(const float* __restrict__ Wd)
{
    __shared__ float tile[32][33];
    const int tx = threadIdx.x;          // 0..31
    const int ty = threadIdx.y;          // 0..7
    const int n0 = blockIdx.x * 32;
    const int k0 = blockIdx.y * 32;

#pragma unroll
    for (int r = 0; r < 4; r++) {
        int k = k0 + ty + r * 8;
        int n = n0 + tx;
        tile[ty + r * 8][tx] = (n < VOCAB) ? Wd[(size_t)k * VOCAB + n] : 0.f;
    }
    __syncthreads();

#pragma unroll
    for (int r = 0; r < 4; r++) {
        int n = n0 + ty + r * 8;
        int k = k0 + tx;
        if (n < VOCAB) {
            float v = tile[tx][ty + r * 8];
            __nv_bfloat16 hi = __float2bfloat16(v);
            g_wth[(size_t)n * HID + k] = hi;
            g_wtl[(size_t)n * HID + k] = __float2bfloat16(v - __bfloat162float(hi));
        }
    }
}

// ---------------- mma.sync GEMM: C = (Yh+Yl) @ (Wth+Wtl)^T + bd --------------
#define GBM 128
#define GBN 128
#define GBK 32
#define ROWB 80                            // bytes per smem row (32 bf16 + pad)
#define MATB (128 * ROWB)                  // 10240 B per matrix tile
#define STAGEB (4 * MATB)                  // Ah, Al, Bh, Bl
#define GSMEM (2 * STAGEB)                 // 81920 B

__global__ void __launch_bounds__(256, 2)
gemm_mma(const __nv_bfloat16* __restrict__ Yh, const __nv_bfloat16* __restrict__ Yl,
         const __nv_bfloat16* __restrict__ Bth, const __nv_bfloat16* __restrict__ Btl,
         const float* __restrict__ bd, float* __restrict__ C)
{
    extern __shared__ __align__(16) char smraw[];
    const uint32_t base = smem_u32(smraw);

    const int tid  = threadIdx.x;
    const int lane = tid & 31;
    const int wid  = tid >> 5;
    const int wm   = wid & 1;              // 0..1
    const int wn   = wid >> 1;             // 0..3
    const int m0   = blockIdx.y * GBM;
    const int n0   = blockIdx.x * GBN;

    float acc[4][4][4];
#pragma unroll
    for (int i = 0; i < 4; i++)
#pragma unroll
        for (int j = 0; j < 4; j++)
#pragma unroll
            for (int q = 0; q < 4; q++)
                acc[i][j][q] = 0.f;

    auto load_stage = [&](int st, int kc) {
        const uint32_t sb = base + st * STAGEB;
        const int kel = kc * GBK;
#pragma unroll
        for (int j = 0; j < 2; j++) {
            int u = tid + j * 256;
            int r = u >> 2;
            int sg = u & 3;
            uint32_t off = (uint32_t)r * ROWB + sg * 16;
            cpa16(sb + 0 * MATB + off, Yh + (size_t)(m0 + r) * HID + kel + sg * 8, 16);
            cpa16(sb + 1 * MATB + off, Yl + (size_t)(m0 + r) * HID + kel + sg * 8, 16);
            int nr = n0 + r;
            uint32_t ok = (nr < VOCAB) ? 16u : 0u;
            size_t br = (nr < VOCAB) ? (size_t)nr : 0;
            cpa16(sb + 2 * MATB + off, Bth + br * HID + kel + sg * 8, ok);
            cpa16(sb + 3 * MATB + off, Btl + br * HID + kel + sg * 8, ok);
        }
        asm volatile("cp.async.commit_group;" ::: "memory");
    };

    load_stage(0, 0);

    const int NKC = HID / GBK;             // 8 chunks
    for (int kc = 0; kc < NKC; kc++) {
        if (kc + 1 < NKC) {
            load_stage((kc + 1) & 1, kc + 1);
            asm volatile("cp.async.wait_group 1;" ::: "memory");
        } else {
            asm volatile("cp.async.wait_group 0;" ::: "memory");
        }
        __syncthreads();

        const uint32_t sb = base + (kc & 1) * STAGEB;
        const uint32_t Ah = sb, Al = sb + MATB, Bh = sb + 2 * MATB, Bl = sb + 3 * MATB;

#pragma unroll
        for (int ks = 0; ks < 2; ks++) {
            const int k0 = ks * 16;
            uint32_t bh[2][4], bl[2][4];
#pragma unroll
            for (int h = 0; h < 2; h++) {
                int row = wn * 32 + h * 16 + ((lane >> 4) & 1) * 8 + (lane & 7);
                int col = k0 + ((lane >> 3) & 1) * 8;
                uint32_t off = (uint32_t)row * ROWB + col * 2;
                ldm_x4(bh[h], Bh + off);
                ldm_x4(bl[h], Bl + off);
            }
#pragma unroll
            for (int mi = 0; mi < 4; mi++) {
                int rowA = wm * 64 + mi * 16 + (lane & 15);
                int colA = k0 + (lane >> 4) * 8;
                uint32_t offA = (uint32_t)rowA * ROWB + colA * 2;
                uint32_t ah[4], al[4];
                ldm_x4(ah, Ah + offA);
                ldm_x4(al, Al + offA);
#pragma unroll
                for (int ni = 0; ni < 4; ni++) {
                    const uint32_t* ph = &bh[ni >> 1][(ni & 1) * 2];
                    const uint32_t* pl = &bl[ni >> 1][(ni & 1) * 2];
                    mma_bf16(acc[mi][ni], ah, ph);   // Ah * Bh
                    mma_bf16(acc[mi][ni], ah, pl);   // Ah * Bl
                    mma_bf16(acc[mi][ni], al, ph);   // Al * Bh
                }
            }
        }
        __syncthreads();
    }

    // ---- epilogue: bias + store ----
    const int g  = lane >> 2;
    const int tq = lane & 3;
#pragma unroll
    for (int mi = 0; mi < 4; mi++) {
        int r0 = m0 + wm * 64 + mi * 16 + g;
#pragma unroll
        for (int ni = 0; ni < 4; ni++) {
            int col = n0 + wn * 32 + ni * 8 + tq * 2;
            if (col < VOCAB) {
                float b0 = bd[col], b1 = bd[col + 1];
                float2 v0 = { acc[mi][ni][0] + b0, acc[mi][ni][1] + b1 };
                float2 v1 = { acc[mi][ni][2] + b0, acc[mi][ni][3] + b1 };
                *(float2*)(C + (size_t)r0 * VOCAB + col) = v0;
                *(float2*)(C + (size_t)(r0 + 8) * VOCAB + col) = v1;
            }
        }
    }
}

// ---------------- launcher ----------------
extern "C" void kernel_launch(void* const* d_in, const int* in_sizes, int n_in,
                              void* d_out, int out_size)
{
    const int*   tokens = (const int*)  d_in[0];  // [32, 512] int32
    const float* state  = (const float*)d_in[1];  // [32, 256]
    const float* Wxh    = (const float*)d_in[2];  // [10000, 256]
    const float* Whh    = (const float*)d_in[3];  // [256, 256]
    const float* bh     = (const float*)d_in[4];  // [256]
    const float* Wd     = (const float*)d_in[5];  // [256, 10000]
    const float* bd     = (const float*)d_in[6];  // [10000]

    float* out  = (float*)d_out;                       // [16384, 10000]
    float* hfin = out + (size_t)MTOT * VOCAB;          // [32, 256]

    cudaFuncSetAttribute(gemm_mma,
                         cudaFuncAttributeMaxDynamicSharedMemorySize, GSMEM);

    __nv_bfloat16 *yh, *yl, *wth, *wtl;
    cudaGetSymbolAddress((void**)&yh,  g_yh);
    cudaGetSymbolAddress((void**)&yl,  g_yl);
    cudaGetSymbolAddress((void**)&wth, g_wth);
    cudaGetSymbolAddress((void**)&wtl, g_wtl);

    rnn_kernel<<<BATCH * 2, 256>>>(tokens, state, Wxh, Whh, bh, hfin);

    dim3 tgrid((VOCAB + 31) / 32, HID / 32);           // (313, 8)
    wd_transpose_split<<<tgrid, dim3(32, 8)>>>(Wd);

    dim3 ggrid((VOCAB + GBN - 1) / GBN, MTOT / GBM);   // (79, 128)
    gemm_mma<<<ggrid, 256, GSMEM>>>(yh, yl, wth, wtl, bd, out);
}

// round 8
// speedup vs baseline: 1.0052x; 1.0052x over previous
#include <cuda_runtime.h>
#include <cuda_bf16.h>
#include <cstdint>

// Problem constants
#define VOCAB 10000
#define HID   256
#define BATCH 32
#define SEQL  512
#define MTOT  (SEQL * BATCH)   // 16384

typedef unsigned long long u64;

// ---------------- scratch (bf16 split operands) ----------------
__device__ __nv_bfloat16 g_yh[(size_t)MTOT * HID];    // Y hi  [M, K]
__device__ __nv_bfloat16 g_yl[(size_t)MTOT * HID];    // Y lo  [M, K]
__device__ __nv_bfloat16 g_wth[(size_t)VOCAB * HID];  // Wd^T hi [N, K]
__device__ __nv_bfloat16 g_wtl[(size_t)VOCAB * HID];  // Wd^T lo [N, K]

// ================= helpers =================
__device__ __forceinline__ uint32_t smem_u32(const void* p) {
    uint32_t a;
    asm("{ .reg .u64 t; cvta.to.shared.u64 t, %1; cvt.u32.u64 %0, t; }"
        : "=r"(a) : "l"(p));
    return a;
}
__device__ __forceinline__ void cpa16(uint32_t dst, const void* src, uint32_t sz) {
    asm volatile("cp.async.cg.shared.global [%0], [%1], 16, %2;"
                 :: "r"(dst), "l"(src), "r"(sz) : "memory");
}
__device__ __forceinline__ void ldm_x4(uint32_t* r, uint32_t addr) {
    asm volatile("ldmatrix.sync.aligned.m8n8.x4.shared.b16 {%0,%1,%2,%3}, [%4];"
                 : "=r"(r[0]), "=r"(r[1]), "=r"(r[2]), "=r"(r[3]) : "r"(addr));
}
__device__ __forceinline__ void mma_bf16(float* c, const uint32_t* a, const uint32_t* b) {
    asm volatile(
        "mma.sync.aligned.m16n8k16.row.col.f32.bf16.bf16.f32 "
        "{%0,%1,%2,%3}, {%4,%5,%6,%7}, {%8,%9}, {%0,%1,%2,%3};"
        : "+f"(c[0]), "+f"(c[1]), "+f"(c[2]), "+f"(c[3])
        : "r"(a[0]), "r"(a[1]), "r"(a[2]), "r"(a[3]), "r"(b[0]), "r"(b[1]));
}
__device__ __forceinline__ u64 packf2(float lo, float hi) {
    u64 d;
    asm("mov.b64 %0, {%1, %2};" : "=l"(d) : "f"(lo), "f"(hi));
    return d;
}
__device__ __forceinline__ void unpackf2(u64 d, float& lo, float& hi) {
    asm("mov.b64 {%0, %1}, %2;" : "=f"(lo), "=f"(hi) : "l"(d));
}
__device__ __forceinline__ u64 fma2(u64 a, u64 b, u64 c) {
    u64 d;
    asm("fma.rn.f32x2 %0, %1, %2, %3;" : "=l"(d) : "l"(a), "l"(b), "l"(c));
    return d;
}
// fast tanh: 1 - 2/(e^{2x}+1); saturates correctly at +-inf
__device__ __forceinline__ float fast_tanh(float x) {
    float z = __expf(2.0f * x);
    return 1.0f - __fdividef(2.0f, z + 1.0f);
}

// ---------------- Recurrence: 1 CTA/batch, 512 threads, split-k lanes -------
// Warp w owns outputs o = w*16 .. w*16+15; lane pairs split k:
// even lane k in [0,128), odd lane k in [128,256). Per thread: 80 Whh values
// in 40 f32x2 regs, 48 from smem (float4 per 4 k's). h double-buffered with
// the upper k-half at +132 floats so even/odd broadcast LDS are 1-phase.
#define KR   80                         // k values in regs per thread
#define KS   (128 - KR)                 // 48 from smem
#define KSQ  (KS / 4)                   // 12 float4 per thread
#define RNN_SMEM (2 * KSQ * HID * 16)   // 98304 bytes

__global__ void __launch_bounds__(512, 1)
rnn_kernel(const int* __restrict__ tokens, const float* __restrict__ state,
           const float* __restrict__ Wxh, const float* __restrict__ Whh,
           const float* __restrict__ bh, float* __restrict__ hfin)
{
    extern __shared__ float4 Wsm4[];             // [2][KSQ][HID]
    __shared__ __align__(16) float hbuf[2][264]; // halves at 0 and 132

    const int b    = blockIdx.x;
    const int tid  = threadIdx.x;
    const int lane = tid & 31;
    const int w    = tid >> 5;                   // 0..15
    const int half = lane & 1;
    const int o    = w * 16 + (lane >> 1);       // output index 0..255
    const int kb   = half * 128;                 // k base
    const int kb_off = half ? 132 : 0;           // h offset in floats
    const int opos = o + ((o >= 128) ? 4 : 0);   // h slot for output o

    // register Whh: k = kb .. kb+KR-1 of column o
    u64 W2[KR / 2];
#pragma unroll
    for (int q = 0; q < KR / 2; q++)
        W2[q] = packf2(Whh[(kb + 2 * q) * HID + o],
                       Whh[(kb + 2 * q + 1) * HID + o]);

    // shared Whh: [half][kq][o] float4 = W[half*128+KR+4kq .. +3][o]
    for (int idx = tid; idx < 2 * KSQ * HID; idx += 512) {
        int hh = idx / (KSQ * HID);
        int rm = idx % (KSQ * HID);
        int kq = rm / HID;
        int oo = rm % HID;
        int k0 = hh * 128 + KR + 4 * kq;
        float4 v;
        v.x = Whh[(k0 + 0) * HID + oo];
        v.y = Whh[(k0 + 1) * HID + oo];
        v.z = Whh[(k0 + 2) * HID + oo];
        v.w = Whh[(k0 + 3) * HID + oo];
        Wsm4[idx] = v;
    }

    const float bias = (half == 0) ? bh[o] : 0.f;
    if (tid < HID)
        hbuf[0][tid + ((tid >= 128) ? 4 : 0)] = state[b * HID + tid];
    __syncthreads();

    const int* toks = tokens + b * SEQL;
    float e = (half == 0) ? Wxh[toks[0] * HID + o] : 0.f;

    const float4* mySm = &Wsm4[(size_t)half * KSQ * HID + o];

    for (int t = 0; t < SEQL; t++) {
        // prefetch next embedding early (covered by this step's work)
        float e_next = 0.f;
        if (half == 0 && t + 1 < SEQL)
            e_next = Wxh[toks[t + 1] * HID + o];

        const ulonglong2* h22 = (const ulonglong2*)(&hbuf[t & 1][kb_off]);

        u64 a0 = packf2(e + bias, 0.f), a1 = 0ull, a2 = 0ull, a3 = 0ull;
        // register part: k = kb .. kb+79  (20 h-vectors, 40 fma2)
#pragma unroll
        for (int q = 0; q < KR / 4; q++) {
            ulonglong2 hv = h22[q];
            a0 = fma2(hv.x, W2[2 * q],     a0);
            a1 = fma2(hv.y, W2[2 * q + 1], a1);
        }
        // shared part: k = kb+80 .. kb+127 (12 h-vectors, 24 fma2)
#pragma unroll
        for (int kq = 0; kq < KSQ; kq++) {
            ulonglong2 hv = h22[KR / 4 + kq];
            float4 wv = mySm[kq * HID];
            const u64* wp = (const u64*)&wv;
            a2 = fma2(hv.x, wp[0], a2);
            a3 = fma2(hv.y, wp[1], a3);
        }

        float s0, s1, s2, s3, s4, s5, s6, s7;
        unpackf2(a0, s0, s1); unpackf2(a1, s2, s3);
        unpackf2(a2, s4, s5); unpackf2(a3, s6, s7);
        float part = ((s0 + s2) + (s1 + s3)) + ((s4 + s6) + (s5 + s7));
        part += __shfl_down_sync(0xffffffffu, part, 1);   // odd -> even

        if (half == 0) {
            float hn = fast_tanh(part);
            hbuf[(t + 1) & 1][opos] = hn;
            size_t oidx = ((size_t)t * BATCH + b) * HID + o;
            __nv_bfloat16 hh2 = __float2bfloat16(hn);
            g_yh[oidx] = hh2;
            g_yl[oidx] = __float2bfloat16(hn - __bfloat162float(hh2));
            if (t == SEQL - 1) hfin[b * HID + o] = hn;
        }
        __syncthreads();
        e = e_next;
    }
}

// ---------------- Wd transpose + bf16 split: [K,N] f32 -> [N,K] bf16 hi/lo --
__global__ void __launch_bounds__(256)
wd_transpose_split(const float* __restrict__ Wd)
{
    __shared__ float tile[32][33];
    const int tx = threadIdx.x;          // 0..31
    const int ty = threadIdx.y;          // 0..7
    const int n0 = blockIdx.x * 32;
    const int k0 = blockIdx.y * 32;

#pragma unroll
    for (int r = 0; r < 4; r++) {
        int k = k0 + ty + r * 8;
        int n = n0 + tx;
        tile[ty + r * 8][tx] = (n < VOCAB) ? Wd[(size_t)k * VOCAB + n] : 0.f;
    }
    __syncthreads();

#pragma unroll
    for (int r = 0; r < 4; r++) {
        int n = n0 + ty + r * 8;
        int k = k0 + tx;
        if (n < VOCAB) {
            float v = tile[tx][ty + r * 8];
            __nv_bfloat16 hi = __float2bfloat16(v);
            g_wth[(size_t)n * HID + k] = hi;
            g_wtl[(size_t)n * HID + k] = __float2bfloat16(v - __bfloat162float(hi));
        }
    }
}

// ---------------- mma.sync GEMM: C = (Yh+Yl) @ (Wth+Wtl)^T + bd --------------
#define GBM 128
#define GBN 128
#define GBK 32
#define ROWB 80                            // bytes per smem row (32 bf16 + pad)
#define MATB (128 * ROWB)                  // 10240 B per matrix tile
#define STAGEB (4 * MATB)                  // Ah, Al, Bh, Bl
#define GSMEM (2 * STAGEB)                 // 81920 B

__global__ void __launch_bounds__(256, 2)
gemm_mma(const __nv_bfloat16* __restrict__ Yh, const __nv_bfloat16* __restrict__ Yl,
         const __nv_bfloat16* __restrict__ Bth, const __nv_bfloat16* __restrict__ Btl,
         const float* __restrict__ bd, float* __restrict__ C)
{
    extern __shared__ __align__(16) char smraw[];
    const uint32_t base = smem_u32(smraw);

    const int tid  = threadIdx.x;
    const int lane = tid & 31;
    const int wid  = tid >> 5;
    const int wm   = wid & 1;              // 0..1
    const int wn   = wid >> 1;             // 0..3
    const int m0   = blockIdx.y * GBM;
    const int n0   = blockIdx.x * GBN;

    float acc[4][4][4];
#pragma unroll
    for (int i = 0; i < 4; i++)
#pragma unroll
        for (int j = 0; j < 4; j++)
#pragma unroll
            for (int q = 0; q < 4; q++)
                acc[i][j][q] = 0.f;

    auto load_stage = [&](int st, int kc) {
        const uint32_t sb = base + st * STAGEB;
        const int kel = kc * GBK;
#pragma unroll
        for (int j = 0; j < 2; j++) {
            int u = tid + j * 256;
            int r = u >> 2;
            int sg = u & 3;
            uint32_t off = (uint32_t)r * ROWB + sg * 16;
            cpa16(sb + 0 * MATB + off, Yh + (size_t)(m0 + r) * HID + kel + sg * 8, 16);
            cpa16(sb + 1 * MATB + off, Yl + (size_t)(m0 + r) * HID + kel + sg * 8, 16);
            int nr = n0 + r;
            uint32_t ok = (nr < VOCAB) ? 16u : 0u;
            size_t br = (nr < VOCAB) ? (size_t)nr : 0;
            cpa16(sb + 2 * MATB + off, Bth + br * HID + kel + sg * 8, ok);
            cpa16(sb + 3 * MATB + off, Btl + br * HID + kel + sg * 8, ok);
        }
        asm volatile("cp.async.commit_group;" ::: "memory");
    };

    load_stage(0, 0);

    const int NKC = HID / GBK;             // 8 chunks
    for (int kc = 0; kc < NKC; kc++) {
        if (kc + 1 < NKC) {
            load_stage((kc + 1) & 1, kc + 1);
            asm volatile("cp.async.wait_group 1;" ::: "memory");
        } else {
            asm volatile("cp.async.wait_group 0;" ::: "memory");
        }
        __syncthreads();

        const uint32_t sb = base + (kc & 1) * STAGEB;
        const uint32_t Ah = sb, Al = sb + MATB, Bh = sb + 2 * MATB, Bl = sb + 3 * MATB;

#pragma unroll
        for (int ks = 0; ks < 2; ks++) {
            const int k0 = ks * 16;
            uint32_t bh[2][4], bl[2][4];
#pragma unroll
            for (int h = 0; h < 2; h++) {
                int row = wn * 32 + h * 16 + ((lane >> 4) & 1) * 8 + (lane & 7);
                int col = k0 + ((lane >> 3) & 1) * 8;
                uint32_t off = (uint32_t)row * ROWB + col * 2;
                ldm_x4(bh[h], Bh + off);
                ldm_x4(bl[h], Bl + off);
            }
#pragma unroll
            for (int mi = 0; mi < 4; mi++) {
                int rowA = wm * 64 + mi * 16 + (lane & 15);
                int colA = k0 + (lane >> 4) * 8;
                uint32_t offA = (uint32_t)rowA * ROWB + colA * 2;
                uint32_t ah[4], al[4];
                ldm_x4(ah, Ah + offA);
                ldm_x4(al, Al + offA);
#pragma unroll
                for (int ni = 0; ni < 4; ni++) {
                    const uint32_t* ph = &bh[ni >> 1][(ni & 1) * 2];
                    const uint32_t* pl = &bl[ni >> 1][(ni & 1) * 2];
                    mma_bf16(acc[mi][ni], ah, ph);   // Ah * Bh
                    mma_bf16(acc[mi][ni], ah, pl);   // Ah * Bl
                    mma_bf16(acc[mi][ni], al, ph);   // Al * Bh
                }
            }
        }
        __syncthreads();
    }

    // ---- epilogue: bias + store ----
    const int g  = lane >> 2;
    const int tq = lane & 3;
#pragma unroll
    for (int mi = 0; mi < 4; mi++) {
        int r0 = m0 + wm * 64 + mi * 16 + g;
#pragma unroll
        for (int ni = 0; ni < 4; ni++) {
            int col = n0 + wn * 32 + ni * 8 + tq * 2;
            if (col < VOCAB) {
                float b0 = bd[col], b1 = bd[col + 1];
                float2 v0 = { acc[mi][ni][0] + b0, acc[mi][ni][1] + b1 };
                float2 v1 = { acc[mi][ni][2] + b0, acc[mi][ni][3] + b1 };
                *(float2*)(C + (size_t)r0 * VOCAB + col) = v0;
                *(float2*)(C + (size_t)(r0 + 8) * VOCAB + col) = v1;
            }
        }
    }
}

// ---------------- launcher ----------------
extern "C" void kernel_launch(void* const* d_in, const int* in_sizes, int n_in,
                              void* d_out, int out_size)
{
    const int*   tokens = (const int*)  d_in[0];  // [32, 512] int32
    const float* state  = (const float*)d_in[1];  // [32, 256]
    const float* Wxh    = (const float*)d_in[2];  // [10000, 256]
    const float* Whh    = (const float*)d_in[3];  // [256, 256]
    const float* bh     = (const float*)d_in[4];  // [256]
    const float* Wd     = (const float*)d_in[5];  // [256, 10000]
    const float* bd     = (const float*)d_in[6];  // [10000]

    float* out  = (float*)d_out;                       // [16384, 10000]
    float* hfin = out + (size_t)MTOT * VOCAB;          // [32, 256]

    cudaFuncSetAttribute(rnn_kernel,
                         cudaFuncAttributeMaxDynamicSharedMemorySize, RNN_SMEM);
    cudaFuncSetAttribute(gemm_mma,
                         cudaFuncAttributeMaxDynamicSharedMemorySize, GSMEM);

    __nv_bfloat16 *yh, *yl, *wth, *wtl;
    cudaGetSymbolAddress((void**)&yh,  g_yh);
    cudaGetSymbolAddress((void**)&yl,  g_yl);
    cudaGetSymbolAddress((void**)&wth, g_wth);
    cudaGetSymbolAddress((void**)&wtl, g_wtl);

    rnn_kernel<<<BATCH, 512, RNN_SMEM>>>(tokens, state, Wxh, Whh, bh, hfin);

    dim3 tgrid((VOCAB + 31) / 32, HID / 32);           // (313, 8)
    wd_transpose_split<<<tgrid, dim3(32, 8)>>>(Wd);

    dim3 ggrid((VOCAB + GBN - 1) / GBN, MTOT / GBM);   // (79, 128)
    gemm_mma<<<ggrid, 256, GSMEM>>>(yh, yl, wth, wtl, bd, out);
}

// round 9
// speedup vs baseline: 1.0313x; 1.0260x over previous
#include <cuda_runtime.h>
#include <cuda_bf16.h>
#include <cstdint>

// Problem constants
#define VOCAB 10000
#define HID   256
#define BATCH 32
#define SEQL  512
#define MTOT  (SEQL * BATCH)   // 16384

typedef unsigned long long u64;

// ---------------- scratch (bf16 split operands) ----------------
__device__ __nv_bfloat16 g_yh[(size_t)MTOT * HID];    // Y hi  [M, K]
__device__ __nv_bfloat16 g_yl[(size_t)MTOT * HID];    // Y lo  [M, K]
__device__ __nv_bfloat16 g_wth[(size_t)VOCAB * HID];  // Wd^T hi [N, K]
__device__ __nv_bfloat16 g_wtl[(size_t)VOCAB * HID];  // Wd^T lo [N, K]

// ================= helpers =================
__device__ __forceinline__ uint32_t smem_u32(const void* p) {
    uint32_t a;
    asm("{ .reg .u64 t; cvta.to.shared.u64 t, %1; cvt.u32.u64 %0, t; }"
        : "=r"(a) : "l"(p));
    return a;
}
__device__ __forceinline__ void cpa16(uint32_t dst, const void* src, uint32_t sz) {
    asm volatile("cp.async.cg.shared.global [%0], [%1], 16, %2;"
                 :: "r"(dst), "l"(src), "r"(sz) : "memory");
}
__device__ __forceinline__ void ldm_x4(uint32_t* r, uint32_t addr) {
    asm volatile("ldmatrix.sync.aligned.m8n8.x4.shared.b16 {%0,%1,%2,%3}, [%4];"
                 : "=r"(r[0]), "=r"(r[1]), "=r"(r[2]), "=r"(r[3]) : "r"(addr));
}
__device__ __forceinline__ void mma_bf16(float* c, const uint32_t* a, const uint32_t* b) {
    asm volatile(
        "mma.sync.aligned.m16n8k16.row.col.f32.bf16.bf16.f32 "
        "{%0,%1,%2,%3}, {%4,%5,%6,%7}, {%8,%9}, {%0,%1,%2,%3};"
        : "+f"(c[0]), "+f"(c[1]), "+f"(c[2]), "+f"(c[3])
        : "r"(a[0]), "r"(a[1]), "r"(a[2]), "r"(a[3]), "r"(b[0]), "r"(b[1]));
}
__device__ __forceinline__ u64 packf2(float lo, float hi) {
    u64 d;
    asm("mov.b64 %0, {%1, %2};" : "=l"(d) : "f"(lo), "f"(hi));
    return d;
}
__device__ __forceinline__ void unpackf2(u64 d, float& lo, float& hi) {
    asm("mov.b64 {%0, %1}, %2;" : "=f"(lo), "=f"(hi) : "l"(d));
}
__device__ __forceinline__ u64 fma2(u64 a, u64 b, u64 c) {
    u64 d;
    asm("fma.rn.f32x2 %0, %1, %2, %3;" : "=l"(d) : "l"(a), "l"(b), "l"(c));
    return d;
}
// fast tanh: 1 - 2/(e^{2x}+1); saturates correctly at +-inf
__device__ __forceinline__ float fast_tanh(float x) {
    float z = __expf(2.0f * x);
    return 1.0f - __fdividef(2.0f, z + 1.0f);
}

// ---------------- Recurrence kernel (R6 version — best measured) ----
#define KREG 128
#define KSH  (HID - KREG)
#define KSHQ (KSH / 4)
#define RNN_SMEM (KSHQ * HID * 16)

__global__ void __launch_bounds__(256, 1)
rnn_kernel(const int* __restrict__ tokens, const float* __restrict__ state,
           const float* __restrict__ Wxh, const float* __restrict__ Whh,
           const float* __restrict__ bh, float* __restrict__ hfin)
{
    extern __shared__ float4 Wsh4[];                 // [KSHQ][HID] float4
    __shared__ __align__(16) float hbuf[2][HID];

    const int b = blockIdx.x;
    const int i = threadIdx.x;

    // Whh rows [0, KREG) for column i, packed as 64 f32x2 pairs
    u64 Wreg2[KREG / 2];
#pragma unroll
    for (int q = 0; q < KREG / 2; q++)
        Wreg2[q] = packf2(Whh[(2 * q) * HID + i], Whh[(2 * q + 1) * HID + i]);

    // Whh rows [KREG, 256) in shared as float4 per (kq, i)
    for (int kq = 0; kq < KSHQ; kq++) {
        float4 v;
        v.x = Whh[(KREG + 4 * kq + 0) * HID + i];
        v.y = Whh[(KREG + 4 * kq + 1) * HID + i];
        v.z = Whh[(KREG + 4 * kq + 2) * HID + i];
        v.w = Whh[(KREG + 4 * kq + 3) * HID + i];
        Wsh4[kq * HID + i] = v;
    }

    const float bias = bh[i];
    hbuf[0][i] = state[b * HID + i];
    __syncthreads();

    const int* toks = tokens + b * SEQL;
    float e = Wxh[toks[0] * HID + i];
    int cur = 0;

    for (int t = 0; t < SEQL; t++) {
        float e_next = (t + 1 < SEQL) ? Wxh[toks[t + 1] * HID + i] : 0.f;

        u64 acc[4];
        acc[0] = packf2(e + bias, 0.f);
        acc[1] = 0ull; acc[2] = 0ull; acc[3] = 0ull;

        const ulonglong2* h22 = (const ulonglong2*)hbuf[cur];

        // register part: k = 0 .. KREG-1
#pragma unroll
        for (int q = 0; q < KREG / 4; q++) {          // q: one float4 of h
            ulonglong2 hv = h22[q];
            acc[0] = fma2(hv.x, Wreg2[2 * q],     acc[0]);
            acc[1] = fma2(hv.y, Wreg2[2 * q + 1], acc[1]);
        }
        // shared part: k = KREG .. 255
#pragma unroll
        for (int kq = 0; kq < KSHQ; kq++) {
            ulonglong2 hv = h22[KREG / 4 + kq];
            float4 wv = Wsh4[kq * HID + i];
            const u64* wp = (const u64*)&wv;
            acc[2] = fma2(hv.x, wp[0], acc[2]);
            acc[3] = fma2(hv.y, wp[1], acc[3]);
        }

        float s0, s1, s2, s3, s4, s5, s6, s7;
        unpackf2(acc[0], s0, s1);
        unpackf2(acc[1], s2, s3);
        unpackf2(acc[2], s4, s5);
        unpackf2(acc[3], s6, s7);
        float sum = ((s0 + s2) + (s1 + s3)) + ((s4 + s6) + (s5 + s7));

        float hn = fast_tanh(sum);
        size_t oidx = ((size_t)t * BATCH + b) * HID + i;
        __nv_bfloat16 hh = __float2bfloat16(hn);
        g_yh[oidx] = hh;
        g_yl[oidx] = __float2bfloat16(hn - __bfloat162float(hh));
        hbuf[cur ^ 1][i] = hn;
        if (t == SEQL - 1) hfin[b * HID + i] = hn;
        __syncthreads();
        cur ^= 1;
        e = e_next;
    }
}

// ---------------- Wd transpose + bf16 split: [K,N] f32 -> [N,K] bf16 hi/lo --
__global__ void __launch_bounds__(256)
wd_transpose_split(const float* __restrict__ Wd)
{
    __shared__ float tile[32][33];
    const int tx = threadIdx.x;          // 0..31
    const int ty = threadIdx.y;          // 0..7
    const int n0 = blockIdx.x * 32;
    const int k0 = blockIdx.y * 32;

#pragma unroll
    for (int r = 0; r < 4; r++) {
        int k = k0 + ty + r * 8;
        int n = n0 + tx;
        tile[ty + r * 8][tx] = (n < VOCAB) ? Wd[(size_t)k * VOCAB + n] : 0.f;
    }
    __syncthreads();

#pragma unroll
    for (int r = 0; r < 4; r++) {
        int n = n0 + ty + r * 8;
        int k = k0 + tx;
        if (n < VOCAB) {
            float v = tile[tx][ty + r * 8];
            __nv_bfloat16 hi = __float2bfloat16(v);
            g_wth[(size_t)n * HID + k] = hi;
            g_wtl[(size_t)n * HID + k] = __float2bfloat16(v - __bfloat162float(hi));
        }
    }
}

// ---------------- mma.sync GEMM: C = (Yh+Yl) @ (Wth+Wtl)^T + bd --------------
// CTA tile 128x256, 8 warps (2x4), warp tile 64x64. K chunks of 32 bf16,
// double-buffered cp.async (1 CTA/SM, 120KB smem). 3-pass bf16 split.
// Per warp-ks: 16 ldm.x4 feed 196K MACs -> tensor-bound (crossbar at ~67%).
#define GBM 128
#define GBN 256
#define GBK 32
#define ROWB 80                            // bytes per smem row (32 bf16 + pad)
#define MATBA (128 * ROWB)                 // 10240 B  (A tile)
#define MATBB (256 * ROWB)                 // 20480 B  (B tile)
#define STAGEB (2 * MATBA + 2 * MATBB)     // 61440 B: [Ah][Al][Bh][Bl]
#define GSMEM (2 * STAGEB)                 // 122880 B

__global__ void __launch_bounds__(256, 1)
gemm_mma(const __nv_bfloat16* __restrict__ Yh, const __nv_bfloat16* __restrict__ Yl,
         const __nv_bfloat16* __restrict__ Bth, const __nv_bfloat16* __restrict__ Btl,
         const float* __restrict__ bd, float* __restrict__ C)
{
    extern __shared__ __align__(16) char smraw[];
    const uint32_t base = smem_u32(smraw);

    const int tid  = threadIdx.x;
    const int lane = tid & 31;
    const int wid  = tid >> 5;
    const int wm   = wid & 1;              // 0..1  (64 rows each)
    const int wn   = wid >> 1;             // 0..3  (64 cols each)
    const int m0   = blockIdx.y * GBM;
    const int n0   = blockIdx.x * GBN;

    float acc[4][8][4];                    // [mi][ni][frag]
#pragma unroll
    for (int i = 0; i < 4; i++)
#pragma unroll
        for (int j = 0; j < 8; j++)
#pragma unroll
            for (int q = 0; q < 4; q++)
                acc[i][j][q] = 0.f;

    // ---- stage loader: 12 cp.async.16B per thread ----
    auto load_stage = [&](int st, int kc) {
        const uint32_t sb = base + st * STAGEB;
        const int kel = kc * GBK;
        // A tiles (h, l): 128 rows x 4 segs = 512 units
#pragma unroll
        for (int j = 0; j < 2; j++) {
            int u = tid + j * 256;
            int r = u >> 2, sg = u & 3;
            uint32_t off = (uint32_t)r * ROWB + sg * 16;
            cpa16(sb + off,         Yh + (size_t)(m0 + r) * HID + kel + sg * 8, 16);
            cpa16(sb + MATBA + off, Yl + (size_t)(m0 + r) * HID + kel + sg * 8, 16);
        }
        // B tiles (h, l): 256 rows x 4 segs = 1024 units
        const uint32_t bb = sb + 2 * MATBA;
#pragma unroll
        for (int j = 0; j < 4; j++) {
            int u = tid + j * 256;
            int r = u >> 2, sg = u & 3;
            uint32_t off = (uint32_t)r * ROWB + sg * 16;
            int nr = n0 + r;
            uint32_t ok = (nr < VOCAB) ? 16u : 0u;
            size_t br = (nr < VOCAB) ? (size_t)nr : 0;
            cpa16(bb + off,         Bth + br * HID + kel + sg * 8, ok);
            cpa16(bb + MATBB + off, Btl + br * HID + kel + sg * 8, ok);
        }
        asm volatile("cp.async.commit_group;" ::: "memory");
    };

    load_stage(0, 0);

    const int NKC = HID / GBK;             // 8 chunks
    for (int kc = 0; kc < NKC; kc++) {
        if (kc + 1 < NKC) {
            load_stage((kc + 1) & 1, kc + 1);
            asm volatile("cp.async.wait_group 1;" ::: "memory");
        } else {
            asm volatile("cp.async.wait_group 0;" ::: "memory");
        }
        __syncthreads();

        const uint32_t sb = base + (kc & 1) * STAGEB;
        const uint32_t Ah = sb, Al = sb + MATBA;
        const uint32_t Bh = sb + 2 * MATBA, Bl = sb + 2 * MATBA + MATBB;

#pragma unroll
        for (int ks = 0; ks < 2; ks++) {
            const int k0 = ks * 16;
            // B fragments: 4 x ldm.x4 per matrix -> 64 cols x 16 k
            uint32_t bh[4][4], bl[4][4];
#pragma unroll
            for (int h = 0; h < 4; h++) {
                int row = wn * 64 + h * 16 + ((lane >> 4) & 1) * 8 + (lane & 7);
                int col = k0 + ((lane >> 3) & 1) * 8;
                uint32_t off = (uint32_t)row * ROWB + col * 2;
                ldm_x4(bh[h], Bh + off);
                ldm_x4(bl[h], Bl + off);
            }
#pragma unroll
            for (int mi = 0; mi < 4; mi++) {
                int rowA = wm * 64 + mi * 16 + (lane & 15);
                int colA = k0 + (lane >> 4) * 8;
                uint32_t offA = (uint32_t)rowA * ROWB + colA * 2;
                uint32_t ah[4], al[4];
                ldm_x4(ah, Ah + offA);
                ldm_x4(al, Al + offA);
#pragma unroll
                for (int ni = 0; ni < 8; ni++) {
                    const uint32_t* ph = &bh[ni >> 1][(ni & 1) * 2];
                    const uint32_t* pl = &bl[ni >> 1][(ni & 1) * 2];
                    mma_bf16(acc[mi][ni], ah, ph);   // Ah * Bh
                    mma_bf16(acc[mi][ni], ah, pl);   // Ah * Bl
                    mma_bf16(acc[mi][ni], al, ph);   // Al * Bh
                }
            }
        }
        __syncthreads();
    }

    // ---- epilogue: bias + store ----
    const int g  = lane >> 2;
    const int tq = lane & 3;
#pragma unroll
    for (int mi = 0; mi < 4; mi++) {
        int r0 = m0 + wm * 64 + mi * 16 + g;
#pragma unroll
        for (int ni = 0; ni < 8; ni++) {
            int col = n0 + wn * 64 + ni * 8 + tq * 2;
            if (col < VOCAB) {
                float b0 = bd[col], b1 = bd[col + 1];
                float2 v0 = { acc[mi][ni][0] + b0, acc[mi][ni][1] + b1 };
                float2 v1 = { acc[mi][ni][2] + b0, acc[mi][ni][3] + b1 };
                *(float2*)(C + (size_t)r0 * VOCAB + col) = v0;
                *(float2*)(C + (size_t)(r0 + 8) * VOCAB + col) = v1;
            }
        }
    }
}

// ---------------- launcher ----------------
extern "C" void kernel_launch(void* const* d_in, const int* in_sizes, int n_in,
                              void* d_out, int out_size)
{
    const int*   tokens = (const int*)  d_in[0];  // [32, 512] int32
    const float* state  = (const float*)d_in[1];  // [32, 256]
    const float* Wxh    = (const float*)d_in[2];  // [10000, 256]
    const float* Whh    = (const float*)d_in[3];  // [256, 256]
    const float* bh     = (const float*)d_in[4];  // [256]
    const float* Wd     = (const float*)d_in[5];  // [256, 10000]
    const float* bd     = (const float*)d_in[6];  // [10000]

    float* out  = (float*)d_out;                       // [16384, 10000]
    float* hfin = out + (size_t)MTOT * VOCAB;          // [32, 256]

    cudaFuncSetAttribute(rnn_kernel,
                         cudaFuncAttributeMaxDynamicSharedMemorySize, RNN_SMEM);
    cudaFuncSetAttribute(gemm_mma,
                         cudaFuncAttributeMaxDynamicSharedMemorySize, GSMEM);

    __nv_bfloat16 *yh, *yl, *wth, *wtl;
    cudaGetSymbolAddress((void**)&yh,  g_yh);
    cudaGetSymbolAddress((void**)&yl,  g_yl);
    cudaGetSymbolAddress((void**)&wth, g_wth);
    cudaGetSymbolAddress((void**)&wtl, g_wtl);

    rnn_kernel<<<BATCH, 256, RNN_SMEM>>>(tokens, state, Wxh, Whh, bh, hfin);

    dim3 tgrid((VOCAB + 31) / 32, HID / 32);           // (313, 8)
    wd_transpose_split<<<tgrid, dim3(32, 8)>>>(Wd);

    dim3 ggrid((VOCAB + GBN - 1) / GBN, MTOT / GBM);   // (40, 128)
    gemm_mma<<<ggrid, 256, GSMEM>>>(yh, yl, wth, wtl, bd, out);
}

// round 10
// speedup vs baseline: 1.3873x; 1.3452x over previous
#include <cuda_runtime.h>
#include <cuda_bf16.h>
#include <cstdint>

// Problem constants
#define VOCAB 10000
#define HID   256
#define BATCH 32
#define SEQL  512
#define MTOT  (SEQL * BATCH)   // 16384
#define NCH   4                // RNN/GEMM pipeline chunks
#define TCH   (SEQL / NCH)     // 128 timesteps per chunk

typedef unsigned long long u64;

// ---------------- scratch ----------------
__device__ __nv_bfloat16 g_yh[(size_t)MTOT * HID];    // Y hi  [M, K]
__device__ __nv_bfloat16 g_yl[(size_t)MTOT * HID];    // Y lo  [M, K]
__device__ __nv_bfloat16 g_wth[(size_t)VOCAB * HID];  // Wd^T hi [N, K]
__device__ __nv_bfloat16 g_wtl[(size_t)VOCAB * HID];  // Wd^T lo [N, K]
__device__ float g_state[BATCH * HID];                // h carried between chunks

// ================= helpers =================
__device__ __forceinline__ uint32_t smem_u32(const void* p) {
    uint32_t a;
    asm("{ .reg .u64 t; cvta.to.shared.u64 t, %1; cvt.u32.u64 %0, t; }"
        : "=r"(a) : "l"(p));
    return a;
}
__device__ __forceinline__ void cpa16(uint32_t dst, const void* src, uint32_t sz) {
    asm volatile("cp.async.cg.shared.global [%0], [%1], 16, %2;"
                 :: "r"(dst), "l"(src), "r"(sz) : "memory");
}
__device__ __forceinline__ void ldm_x4(uint32_t* r, uint32_t addr) {
    asm volatile("ldmatrix.sync.aligned.m8n8.x4.shared.b16 {%0,%1,%2,%3}, [%4];"
                 : "=r"(r[0]), "=r"(r[1]), "=r"(r[2]), "=r"(r[3]) : "r"(addr));
}
__device__ __forceinline__ void mma_bf16(float* c, const uint32_t* a, const uint32_t* b) {
    asm volatile(
        "mma.sync.aligned.m16n8k16.row.col.f32.bf16.bf16.f32 "
        "{%0,%1,%2,%3}, {%4,%5,%6,%7}, {%8,%9}, {%0,%1,%2,%3};"
        : "+f"(c[0]), "+f"(c[1]), "+f"(c[2]), "+f"(c[3])
        : "r"(a[0]), "r"(a[1]), "r"(a[2]), "r"(a[3]), "r"(b[0]), "r"(b[1]));
}
__device__ __forceinline__ u64 packf2(float lo, float hi) {
    u64 d;
    asm("mov.b64 %0, {%1, %2};" : "=l"(d) : "f"(lo), "f"(hi));
    return d;
}
__device__ __forceinline__ void unpackf2(u64 d, float& lo, float& hi) {
    asm("mov.b64 {%0, %1}, %2;" : "=f"(lo), "=f"(hi) : "l"(d));
}
__device__ __forceinline__ u64 fma2(u64 a, u64 b, u64 c) {
    u64 d;
    asm("fma.rn.f32x2 %0, %1, %2, %3;" : "=l"(d) : "l"(a), "l"(b), "l"(c));
    return d;
}
// fast tanh: 1 - 2/(e^{2x}+1); saturates correctly at +-inf
__device__ __forceinline__ float fast_tanh(float x) {
    float z = __expf(2.0f * x);
    return 1.0f - __fdividef(2.0f, z + 1.0f);
}

// ---------------- Recurrence chunk kernel (R6 core, t in [t0, t0+TCH)) ----
#define KREG 128
#define KSH  (HID - KREG)
#define KSHQ (KSH / 4)
#define RNN_SMEM (KSHQ * HID * 16)

__global__ void __launch_bounds__(256, 1)
rnn_kernel(const int* __restrict__ tokens, const float* __restrict__ state,
           const float* __restrict__ Wxh, const float* __restrict__ Whh,
           const float* __restrict__ bh, float* __restrict__ hfin, int t0)
{
    extern __shared__ float4 Wsh4[];                 // [KSHQ][HID] float4
    __shared__ __align__(16) float hbuf[2][HID];

    const int b = blockIdx.x;
    const int i = threadIdx.x;

    // Whh rows [0, KREG) for column i, packed as 64 f32x2 pairs
    u64 Wreg2[KREG / 2];
#pragma unroll
    for (int q = 0; q < KREG / 2; q++)
        Wreg2[q] = packf2(Whh[(2 * q) * HID + i], Whh[(2 * q + 1) * HID + i]);

    // Whh rows [KREG, 256) in shared as float4 per (kq, i)
    for (int kq = 0; kq < KSHQ; kq++) {
        float4 v;
        v.x = Whh[(KREG + 4 * kq + 0) * HID + i];
        v.y = Whh[(KREG + 4 * kq + 1) * HID + i];
        v.z = Whh[(KREG + 4 * kq + 2) * HID + i];
        v.w = Whh[(KREG + 4 * kq + 3) * HID + i];
        Wsh4[kq * HID + i] = v;
    }

    const float bias = bh[i];
    hbuf[0][i] = (t0 == 0) ? state[b * HID + i] : g_state[b * HID + i];
    __syncthreads();

    const int* toks = tokens + b * SEQL;
    float e = Wxh[toks[t0] * HID + i];
    int cur = 0;
    float hn = 0.f;

    const int tend = t0 + TCH;
    for (int t = t0; t < tend; t++) {
        float e_next = (t + 1 < SEQL) ? Wxh[toks[t + 1] * HID + i] : 0.f;

        u64 acc[4];
        acc[0] = packf2(e + bias, 0.f);
        acc[1] = 0ull; acc[2] = 0ull; acc[3] = 0ull;

        const ulonglong2* h22 = (const ulonglong2*)hbuf[cur];

#pragma unroll
        for (int q = 0; q < KREG / 4; q++) {
            ulonglong2 hv = h22[q];
            acc[0] = fma2(hv.x, Wreg2[2 * q],     acc[0]);
            acc[1] = fma2(hv.y, Wreg2[2 * q + 1], acc[1]);
        }
#pragma unroll
        for (int kq = 0; kq < KSHQ; kq++) {
            ulonglong2 hv = h22[KREG / 4 + kq];
            float4 wv = Wsh4[kq * HID + i];
            const u64* wp = (const u64*)&wv;
            acc[2] = fma2(hv.x, wp[0], acc[2]);
            acc[3] = fma2(hv.y, wp[1], acc[3]);
        }

        float s0, s1, s2, s3, s4, s5, s6, s7;
        unpackf2(acc[0], s0, s1);
        unpackf2(acc[1], s2, s3);
        unpackf2(acc[2], s4, s5);
        unpackf2(acc[3], s6, s7);
        float sum = ((s0 + s2) + (s1 + s3)) + ((s4 + s6) + (s5 + s7));

        hn = fast_tanh(sum);
        size_t oidx = ((size_t)t * BATCH + b) * HID + i;
        __nv_bfloat16 hh = __float2bfloat16(hn);
        g_yh[oidx] = hh;
        g_yl[oidx] = __float2bfloat16(hn - __bfloat162float(hh));
        hbuf[cur ^ 1][i] = hn;
        __syncthreads();
        cur ^= 1;
        e = e_next;
    }

    // carry state to next chunk / final output
    g_state[b * HID + i] = hn;
    if (tend == SEQL) hfin[b * HID + i] = hn;
}

// ---------------- Wd transpose + bf16 split: [K,N] f32 -> [N,K] bf16 hi/lo --
__global__ void __launch_bounds__(256)
wd_transpose_split(const float* __restrict__ Wd)
{
    __shared__ float tile[32][33];
    const int tx = threadIdx.x;          // 0..31
    const int ty = threadIdx.y;          // 0..7
    const int n0 = blockIdx.x * 32;
    const int k0 = blockIdx.y * 32;

#pragma unroll
    for (int r = 0; r < 4; r++) {
        int k = k0 + ty + r * 8;
        int n = n0 + tx;
        tile[ty + r * 8][tx] = (n < VOCAB) ? Wd[(size_t)k * VOCAB + n] : 0.f;
    }
    __syncthreads();

#pragma unroll
    for (int r = 0; r < 4; r++) {
        int n = n0 + ty + r * 8;
        int k = k0 + tx;
        if (n < VOCAB) {
            float v = tile[tx][ty + r * 8];
            __nv_bfloat16 hi = __float2bfloat16(v);
            g_wth[(size_t)n * HID + k] = hi;
            g_wtl[(size_t)n * HID + k] = __float2bfloat16(v - __bfloat162float(hi));
        }
    }
}

// ---------------- mma.sync GEMM (R6 config: 128x128, 2 CTA/SM) --------------
#define GBM 128
#define GBN 128
#define GBK 32
#define ROWB 80                            // bytes per smem row (32 bf16 + pad)
#define MATB (128 * ROWB)                  // 10240 B per matrix tile
#define STAGEB (4 * MATB)                  // Ah, Al, Bh, Bl
#define GSMEM (2 * STAGEB)                 // 81920 B

__global__ void __launch_bounds__(256, 2)
gemm_mma(const __nv_bfloat16* __restrict__ Yh, const __nv_bfloat16* __restrict__ Yl,
         const __nv_bfloat16* __restrict__ Bth, const __nv_bfloat16* __restrict__ Btl,
         const float* __restrict__ bd, float* __restrict__ C, int m_base)
{
    extern __shared__ __align__(16) char smraw[];
    const uint32_t base = smem_u32(smraw);

    const int tid  = threadIdx.x;
    const int lane = tid & 31;
    const int wid  = tid >> 5;
    const int wm   = wid & 1;              // 0..1
    const int wn   = wid >> 1;             // 0..3
    const int m0   = m_base + blockIdx.y * GBM;
    const int n0   = blockIdx.x * GBN;

    float acc[4][4][4];
#pragma unroll
    for (int i = 0; i < 4; i++)
#pragma unroll
        for (int j = 0; j < 4; j++)
#pragma unroll
            for (int q = 0; q < 4; q++)
                acc[i][j][q] = 0.f;

    auto load_stage = [&](int st, int kc) {
        const uint32_t sb = base + st * STAGEB;
        const int kel = kc * GBK;
#pragma unroll
        for (int j = 0; j < 2; j++) {
            int u = tid + j * 256;
            int r = u >> 2;
            int sg = u & 3;
            uint32_t off = (uint32_t)r * ROWB + sg * 16;
            cpa16(sb + 0 * MATB + off, Yh + (size_t)(m0 + r) * HID + kel + sg * 8, 16);
            cpa16(sb + 1 * MATB + off, Yl + (size_t)(m0 + r) * HID + kel + sg * 8, 16);
            int nr = n0 + r;
            uint32_t ok = (nr < VOCAB) ? 16u : 0u;
            size_t br = (nr < VOCAB) ? (size_t)nr : 0;
            cpa16(sb + 2 * MATB + off, Bth + br * HID + kel + sg * 8, ok);
            cpa16(sb + 3 * MATB + off, Btl + br * HID + kel + sg * 8, ok);
        }
        asm volatile("cp.async.commit_group;" ::: "memory");
    };

    load_stage(0, 0);

    const int NKC = HID / GBK;             // 8 chunks
    for (int kc = 0; kc < NKC; kc++) {
        if (kc + 1 < NKC) {
            load_stage((kc + 1) & 1, kc + 1);
            asm volatile("cp.async.wait_group 1;" ::: "memory");
        } else {
            asm volatile("cp.async.wait_group 0;" ::: "memory");
        }
        __syncthreads();

        const uint32_t sb = base + (kc & 1) * STAGEB;
        const uint32_t Ah = sb, Al = sb + MATB, Bh = sb + 2 * MATB, Bl = sb + 3 * MATB;

#pragma unroll
        for (int ks = 0; ks < 2; ks++) {
            const int k0 = ks * 16;
            uint32_t bh[2][4], bl[2][4];
#pragma unroll
            for (int h = 0; h < 2; h++) {
                int row = wn * 32 + h * 16 + ((lane >> 4) & 1) * 8 + (lane & 7);
                int col = k0 + ((lane >> 3) & 1) * 8;
                uint32_t off = (uint32_t)row * ROWB + col * 2;
                ldm_x4(bh[h], Bh + off);
                ldm_x4(bl[h], Bl + off);
            }
#pragma unroll
            for (int mi = 0; mi < 4; mi++) {
                int rowA = wm * 64 + mi * 16 + (lane & 15);
                int colA = k0 + (lane >> 4) * 8;
                uint32_t offA = (uint32_t)rowA * ROWB + colA * 2;
                uint32_t ah[4], al[4];
                ldm_x4(ah, Ah + offA);
                ldm_x4(al, Al + offA);
#pragma unroll
                for (int ni = 0; ni < 4; ni++) {
                    const uint32_t* ph = &bh[ni >> 1][(ni & 1) * 2];
                    const uint32_t* pl = &bl[ni >> 1][(ni & 1) * 2];
                    mma_bf16(acc[mi][ni], ah, ph);   // Ah * Bh
                    mma_bf16(acc[mi][ni], ah, pl);   // Ah * Bl
                    mma_bf16(acc[mi][ni], al, ph);   // Al * Bh
                }
            }
        }
        __syncthreads();
    }

    // ---- epilogue: bias + store ----
    const int g  = lane >> 2;
    const int tq = lane & 3;
#pragma unroll
    for (int mi = 0; mi < 4; mi++) {
        int r0 = m0 + wm * 64 + mi * 16 + g;
#pragma unroll
        for (int ni = 0; ni < 4; ni++) {
            int col = n0 + wn * 32 + ni * 8 + tq * 2;
            if (col < VOCAB) {
                float b0 = bd[col], b1 = bd[col + 1];
                float2 v0 = { acc[mi][ni][0] + b0, acc[mi][ni][1] + b1 };
                float2 v1 = { acc[mi][ni][2] + b0, acc[mi][ni][3] + b1 };
                *(float2*)(C + (size_t)r0 * VOCAB + col) = v0;
                *(float2*)(C + (size_t)(r0 + 8) * VOCAB + col) = v1;
            }
        }
    }
}

// ---------------- stream/event plumbing (created pre-main, no device allocs
// inside kernel_launch; events are timing-disabled for graph capture) -------
struct PipeResources {
    cudaStream_t s2;
    cudaEvent_t evRoot, evR[NCH], evDone;
    PipeResources() {
        cudaStreamCreateWithFlags(&s2, cudaStreamNonBlocking);
        cudaEventCreateWithFlags(&evRoot, cudaEventDisableTiming);
        for (int c = 0; c < NCH; c++)
            cudaEventCreateWithFlags(&evR[c], cudaEventDisableTiming);
        cudaEventCreateWithFlags(&evDone, cudaEventDisableTiming);
    }
};
static PipeResources g_pipe;

// ---------------- launcher: fork-join RNN/GEMM pipeline ----------------
extern "C" void kernel_launch(void* const* d_in, const int* in_sizes, int n_in,
                              void* d_out, int out_size)
{
    const int*   tokens = (const int*)  d_in[0];  // [32, 512] int32
    const float* state  = (const float*)d_in[1];  // [32, 256]
    const float* Wxh    = (const float*)d_in[2];  // [10000, 256]
    const float* Whh    = (const float*)d_in[3];  // [256, 256]
    const float* bh     = (const float*)d_in[4];  // [256]
    const float* Wd     = (const float*)d_in[5];  // [256, 10000]
    const float* bd     = (const float*)d_in[6];  // [10000]

    float* out  = (float*)d_out;                       // [16384, 10000]
    float* hfin = out + (size_t)MTOT * VOCAB;          // [32, 256]

    cudaFuncSetAttribute(rnn_kernel,
                         cudaFuncAttributeMaxDynamicSharedMemorySize, RNN_SMEM);
    cudaFuncSetAttribute(gemm_mma,
                         cudaFuncAttributeMaxDynamicSharedMemorySize, GSMEM);

    __nv_bfloat16 *yh, *yl, *wth, *wtl;
    cudaGetSymbolAddress((void**)&yh,  g_yh);
    cudaGetSymbolAddress((void**)&yl,  g_yl);
    cudaGetSymbolAddress((void**)&wth, g_wth);
    cudaGetSymbolAddress((void**)&wtl, g_wtl);

    cudaStream_t s2 = g_pipe.s2;

    // fork: s2 joins the capture DAG off the default stream
    cudaEventRecord(g_pipe.evRoot, 0);
    cudaStreamWaitEvent(s2, g_pipe.evRoot, 0);

    // transpose (independent of RNN) on s2
    dim3 tgrid((VOCAB + 31) / 32, HID / 32);           // (313, 8)
    wd_transpose_split<<<tgrid, dim3(32, 8), 0, s2>>>(Wd);

    dim3 ggrid((VOCAB + GBN - 1) / GBN, (MTOT / NCH) / GBM);   // (79, 32)
    for (int c = 0; c < NCH; c++) {
        // RNN chunk c on default stream (serial chain)
        rnn_kernel<<<BATCH, 256, RNN_SMEM>>>(tokens, state, Wxh, Whh, bh,
                                             hfin, c * TCH);
        cudaEventRecord(g_pipe.evR[c], 0);
        // GEMM chunk c on s2, gated on RNN chunk c
        cudaStreamWaitEvent(s2, g_pipe.evR[c], 0);
        gemm_mma<<<ggrid, 256, GSMEM, s2>>>(yh, yl, wth, wtl, bd, out,
                                            c * (MTOT / NCH));
    }

    // join: default stream waits for the GEMM stream
    cudaEventRecord(g_pipe.evDone, s2);
    cudaStreamWaitEvent(0, g_pipe.evDone, 0);
}

// round 11
// speedup vs baseline: 1.4455x; 1.0419x over previous
#include <cuda_runtime.h>
#include <cuda_bf16.h>
#include <cstdint>

// Problem constants
#define VOCAB 10000
#define HID   256
#define BATCH 32
#define SEQL  512
#define MTOT  (SEQL * BATCH)   // 16384
#define NCH   8                // RNN/GEMM pipeline chunks
#define TCH   (SEQL / NCH)     // 64 timesteps per chunk

typedef unsigned long long u64;

// ---------------- scratch ----------------
__device__ __nv_bfloat16 g_yh[(size_t)MTOT * HID];    // Y hi  [M, K]
__device__ __nv_bfloat16 g_yl[(size_t)MTOT * HID];    // Y lo  [M, K]
__device__ __nv_bfloat16 g_wth[(size_t)VOCAB * HID];  // Wd^T hi [N, K]
__device__ __nv_bfloat16 g_wtl[(size_t)VOCAB * HID];  // Wd^T lo [N, K]
__device__ float g_state[BATCH * HID];                // h carried between chunks

// ================= helpers =================
__device__ __forceinline__ uint32_t smem_u32(const void* p) {
    uint32_t a;
    asm("{ .reg .u64 t; cvta.to.shared.u64 t, %1; cvt.u32.u64 %0, t; }"
        : "=r"(a) : "l"(p));
    return a;
}
__device__ __forceinline__ void cpa16(uint32_t dst, const void* src, uint32_t sz) {
    asm volatile("cp.async.cg.shared.global [%0], [%1], 16, %2;"
                 :: "r"(dst), "l"(src), "r"(sz) : "memory");
}
__device__ __forceinline__ void ldm_x4(uint32_t* r, uint32_t addr) {
    asm volatile("ldmatrix.sync.aligned.m8n8.x4.shared.b16 {%0,%1,%2,%3}, [%4];"
                 : "=r"(r[0]), "=r"(r[1]), "=r"(r[2]), "=r"(r[3]) : "r"(addr));
}
__device__ __forceinline__ void mma_bf16(float* c, const uint32_t* a, const uint32_t* b) {
    asm volatile(
        "mma.sync.aligned.m16n8k16.row.col.f32.bf16.bf16.f32 "
        "{%0,%1,%2,%3}, {%4,%5,%6,%7}, {%8,%9}, {%0,%1,%2,%3};"
        : "+f"(c[0]), "+f"(c[1]), "+f"(c[2]), "+f"(c[3])
        : "r"(a[0]), "r"(a[1]), "r"(a[2]), "r"(a[3]), "r"(b[0]), "r"(b[1]));
}
__device__ __forceinline__ u64 packf2(float lo, float hi) {
    u64 d;
    asm("mov.b64 %0, {%1, %2};" : "=l"(d) : "f"(lo), "f"(hi));
    return d;
}
__device__ __forceinline__ void unpackf2(u64 d, float& lo, float& hi) {
    asm("mov.b64 {%0, %1}, %2;" : "=f"(lo), "=f"(hi) : "l"(d));
}
__device__ __forceinline__ u64 fma2(u64 a, u64 b, u64 c) {
    u64 d;
    asm("fma.rn.f32x2 %0, %1, %2, %3;" : "=l"(d) : "l"(a), "l"(b), "l"(c));
    return d;
}
// fast tanh: 1 - 2/(e^{2x}+1); saturates correctly at +-inf
__device__ __forceinline__ float fast_tanh(float x) {
    float z = __expf(2.0f * x);
    return 1.0f - __fdividef(2.0f, z + 1.0f);
}

// ---------------- Recurrence chunk kernel (R6 core, t in [t0, t0+TCH)) ----
// Dynamic smem is over-allocated to 152KB (only 128KB used) so that no
// gemm_mma CTA (80KB) can co-reside on an RNN SM -> no crossbar contention.
#define KREG 128
#define KSH  (HID - KREG)
#define KSHQ (KSH / 4)
#define RNN_SMEM_USED (KSHQ * HID * 16)          // 131072
#define RNN_SMEM_ALLOC (152 * 1024)              // exclusion padding

__global__ void __launch_bounds__(256, 1)
rnn_kernel(const int* __restrict__ tokens, const float* __restrict__ state,
           const float* __restrict__ Wxh, const float* __restrict__ Whh,
           const float* __restrict__ bh, float* __restrict__ hfin, int t0)
{
    extern __shared__ float4 Wsh4[];                 // [KSHQ][HID] float4
    __shared__ __align__(16) float hbuf[2][HID];

    const int b = blockIdx.x;
    const int i = threadIdx.x;

    // Whh rows [0, KREG) for column i, packed as 64 f32x2 pairs
    u64 Wreg2[KREG / 2];
#pragma unroll
    for (int q = 0; q < KREG / 2; q++)
        Wreg2[q] = packf2(Whh[(2 * q) * HID + i], Whh[(2 * q + 1) * HID + i]);

    // Whh rows [KREG, 256) in shared as float4 per (kq, i)
    for (int kq = 0; kq < KSHQ; kq++) {
        float4 v;
        v.x = Whh[(KREG + 4 * kq + 0) * HID + i];
        v.y = Whh[(KREG + 4 * kq + 1) * HID + i];
        v.z = Whh[(KREG + 4 * kq + 2) * HID + i];
        v.w = Whh[(KREG + 4 * kq + 3) * HID + i];
        Wsh4[kq * HID + i] = v;
    }

    const float bias = bh[i];
    hbuf[0][i] = (t0 == 0) ? state[b * HID + i] : g_state[b * HID + i];
    __syncthreads();

    const int* toks = tokens + b * SEQL;
    float e = Wxh[toks[t0] * HID + i];
    int cur = 0;
    float hn = 0.f;

    const int tend = t0 + TCH;
    for (int t = t0; t < tend; t++) {
        float e_next = (t + 1 < SEQL) ? Wxh[toks[t + 1] * HID + i] : 0.f;

        u64 acc[4];
        acc[0] = packf2(e + bias, 0.f);
        acc[1] = 0ull; acc[2] = 0ull; acc[3] = 0ull;

        const ulonglong2* h22 = (const ulonglong2*)hbuf[cur];

#pragma unroll
        for (int q = 0; q < KREG / 4; q++) {
            ulonglong2 hv = h22[q];
            acc[0] = fma2(hv.x, Wreg2[2 * q],     acc[0]);
            acc[1] = fma2(hv.y, Wreg2[2 * q + 1], acc[1]);
        }
#pragma unroll
        for (int kq = 0; kq < KSHQ; kq++) {
            ulonglong2 hv = h22[KREG / 4 + kq];
            float4 wv = Wsh4[kq * HID + i];
            const u64* wp = (const u64*)&wv;
            acc[2] = fma2(hv.x, wp[0], acc[2]);
            acc[3] = fma2(hv.y, wp[1], acc[3]);
        }

        float s0, s1, s2, s3, s4, s5, s6, s7;
        unpackf2(acc[0], s0, s1);
        unpackf2(acc[1], s2, s3);
        unpackf2(acc[2], s4, s5);
        unpackf2(acc[3], s6, s7);
        float sum = ((s0 + s2) + (s1 + s3)) + ((s4 + s6) + (s5 + s7));

        hn = fast_tanh(sum);
        size_t oidx = ((size_t)t * BATCH + b) * HID + i;
        __nv_bfloat16 hh = __float2bfloat16(hn);
        g_yh[oidx] = hh;
        g_yl[oidx] = __float2bfloat16(hn - __bfloat162float(hh));
        hbuf[cur ^ 1][i] = hn;
        __syncthreads();
        cur ^= 1;
        e = e_next;
    }

    // carry state to next chunk / final output
    g_state[b * HID + i] = hn;
    if (tend == SEQL) hfin[b * HID + i] = hn;
}

// ---------------- Wd transpose + bf16 split: [K,N] f32 -> [N,K] bf16 hi/lo --
__global__ void __launch_bounds__(256)
wd_transpose_split(const float* __restrict__ Wd)
{
    __shared__ float tile[32][33];
    const int tx = threadIdx.x;          // 0..31
    const int ty = threadIdx.y;          // 0..7
    const int n0 = blockIdx.x * 32;
    const int k0 = blockIdx.y * 32;

#pragma unroll
    for (int r = 0; r < 4; r++) {
        int k = k0 + ty + r * 8;
        int n = n0 + tx;
        tile[ty + r * 8][tx] = (n < VOCAB) ? Wd[(size_t)k * VOCAB + n] : 0.f;
    }
    __syncthreads();

#pragma unroll
    for (int r = 0; r < 4; r++) {
        int n = n0 + ty + r * 8;
        int k = k0 + tx;
        if (n < VOCAB) {
            float v = tile[tx][ty + r * 8];
            __nv_bfloat16 hi = __float2bfloat16(v);
            g_wth[(size_t)n * HID + k] = hi;
            g_wtl[(size_t)n * HID + k] = __float2bfloat16(v - __bfloat162float(hi));
        }
    }
}

// ---------------- mma.sync GEMM (R6 config: 128x128, 2 CTA/SM) --------------
#define GBM 128
#define GBN 128
#define GBK 32
#define ROWB 80                            // bytes per smem row (32 bf16 + pad)
#define MATB (128 * ROWB)                  // 10240 B per matrix tile
#define STAGEB (4 * MATB)                  // Ah, Al, Bh, Bl
#define GSMEM (2 * STAGEB)                 // 81920 B

__global__ void __launch_bounds__(256, 2)
gemm_mma(const __nv_bfloat16* __restrict__ Yh, const __nv_bfloat16* __restrict__ Yl,
         const __nv_bfloat16* __restrict__ Bth, const __nv_bfloat16* __restrict__ Btl,
         const float* __restrict__ bd, float* __restrict__ C, int m_base)
{
    extern __shared__ __align__(16) char smraw[];
    const uint32_t base = smem_u32(smraw);

    const int tid  = threadIdx.x;
    const int lane = tid & 31;
    const int wid  = tid >> 5;
    const int wm   = wid & 1;              // 0..1
    const int wn   = wid >> 1;             // 0..3
    const int m0   = m_base + blockIdx.y * GBM;
    const int n0   = blockIdx.x * GBN;

    float acc[4][4][4];
#pragma unroll
    for (int i = 0; i < 4; i++)
#pragma unroll
        for (int j = 0; j < 4; j++)
#pragma unroll
            for (int q = 0; q < 4; q++)
                acc[i][j][q] = 0.f;

    auto load_stage = [&](int st, int kc) {
        const uint32_t sb = base + st * STAGEB;
        const int kel = kc * GBK;
#pragma unroll
        for (int j = 0; j < 2; j++) {
            int u = tid + j * 256;
            int r = u >> 2;
            int sg = u & 3;
            uint32_t off = (uint32_t)r * ROWB + sg * 16;
            cpa16(sb + 0 * MATB + off, Yh + (size_t)(m0 + r) * HID + kel + sg * 8, 16);
            cpa16(sb + 1 * MATB + off, Yl + (size_t)(m0 + r) * HID + kel + sg * 8, 16);
            int nr = n0 + r;
            uint32_t ok = (nr < VOCAB) ? 16u : 0u;
            size_t br = (nr < VOCAB) ? (size_t)nr : 0;
            cpa16(sb + 2 * MATB + off, Bth + br * HID + kel + sg * 8, ok);
            cpa16(sb + 3 * MATB + off, Btl + br * HID + kel + sg * 8, ok);
        }
        asm volatile("cp.async.commit_group;" ::: "memory");
    };

    load_stage(0, 0);

    const int NKC = HID / GBK;             // 8 chunks
    for (int kc = 0; kc < NKC; kc++) {
        if (kc + 1 < NKC) {
            load_stage((kc + 1) & 1, kc + 1);
            asm volatile("cp.async.wait_group 1;" ::: "memory");
        } else {
            asm volatile("cp.async.wait_group 0;" ::: "memory");
        }
        __syncthreads();

        const uint32_t sb = base + (kc & 1) * STAGEB;
        const uint32_t Ah = sb, Al = sb + MATB, Bh = sb + 2 * MATB, Bl = sb + 3 * MATB;

#pragma unroll
        for (int ks = 0; ks < 2; ks++) {
            const int k0 = ks * 16;
            uint32_t bh[2][4], bl[2][4];
#pragma unroll
            for (int h = 0; h < 2; h++) {
                int row = wn * 32 + h * 16 + ((lane >> 4) & 1) * 8 + (lane & 7);
                int col = k0 + ((lane >> 3) & 1) * 8;
                uint32_t off = (uint32_t)row * ROWB + col * 2;
                ldm_x4(bh[h], Bh + off);
                ldm_x4(bl[h], Bl + off);
            }
#pragma unroll
            for (int mi = 0; mi < 4; mi++) {
                int rowA = wm * 64 + mi * 16 + (lane & 15);
                int colA = k0 + (lane >> 4) * 8;
                uint32_t offA = (uint32_t)rowA * ROWB + colA * 2;
                uint32_t ah[4], al[4];
                ldm_x4(ah, Ah + offA);
                ldm_x4(al, Al + offA);
#pragma unroll
                for (int ni = 0; ni < 4; ni++) {
                    const uint32_t* ph = &bh[ni >> 1][(ni & 1) * 2];
                    const uint32_t* pl = &bl[ni >> 1][(ni & 1) * 2];
                    mma_bf16(acc[mi][ni], ah, ph);   // Ah * Bh
                    mma_bf16(acc[mi][ni], ah, pl);   // Ah * Bl
                    mma_bf16(acc[mi][ni], al, ph);   // Al * Bh
                }
            }
        }
        __syncthreads();
    }

    // ---- epilogue: bias + store ----
    const int g  = lane >> 2;
    const int tq = lane & 3;
#pragma unroll
    for (int mi = 0; mi < 4; mi++) {
        int r0 = m0 + wm * 64 + mi * 16 + g;
#pragma unroll
        for (int ni = 0; ni < 4; ni++) {
            int col = n0 + wn * 32 + ni * 8 + tq * 2;
            if (col < VOCAB) {
                float b0 = bd[col], b1 = bd[col + 1];
                float2 v0 = { acc[mi][ni][0] + b0, acc[mi][ni][1] + b1 };
                float2 v1 = { acc[mi][ni][2] + b0, acc[mi][ni][3] + b1 };
                *(float2*)(C + (size_t)r0 * VOCAB + col) = v0;
                *(float2*)(C + (size_t)(r0 + 8) * VOCAB + col) = v1;
            }
        }
    }
}

// ---------------- stream/event plumbing (created pre-main, no device allocs
// inside kernel_launch; events are timing-disabled for graph capture) -------
struct PipeResources {
    cudaStream_t s2;
    cudaEvent_t evRoot, evR[NCH], evDone;
    PipeResources() {
        cudaStreamCreateWithFlags(&s2, cudaStreamNonBlocking);
        cudaEventCreateWithFlags(&evRoot, cudaEventDisableTiming);
        for (int c = 0; c < NCH; c++)
            cudaEventCreateWithFlags(&evR[c], cudaEventDisableTiming);
        cudaEventCreateWithFlags(&evDone, cudaEventDisableTiming);
    }
};
static PipeResources g_pipe;

// ---------------- launcher: fork-join RNN/GEMM pipeline ----------------
extern "C" void kernel_launch(void* const* d_in, const int* in_sizes, int n_in,
                              void* d_out, int out_size)
{
    const int*   tokens = (const int*)  d_in[0];  // [32, 512] int32
    const float* state  = (const float*)d_in[1];  // [32, 256]
    const float* Wxh    = (const float*)d_in[2];  // [10000, 256]
    const float* Whh    = (const float*)d_in[3];  // [256, 256]
    const float* bh     = (const float*)d_in[4];  // [256]
    const float* Wd     = (const float*)d_in[5];  // [256, 10000]
    const float* bd     = (const float*)d_in[6];  // [10000]

    float* out  = (float*)d_out;                       // [16384, 10000]
    float* hfin = out + (size_t)MTOT * VOCAB;          // [32, 256]

    cudaFuncSetAttribute(rnn_kernel,
                         cudaFuncAttributeMaxDynamicSharedMemorySize, RNN_SMEM_ALLOC);
    cudaFuncSetAttribute(gemm_mma,
                         cudaFuncAttributeMaxDynamicSharedMemorySize, GSMEM);

    __nv_bfloat16 *yh, *yl, *wth, *wtl;
    cudaGetSymbolAddress((void**)&yh,  g_yh);
    cudaGetSymbolAddress((void**)&yl,  g_yl);
    cudaGetSymbolAddress((void**)&wth, g_wth);
    cudaGetSymbolAddress((void**)&wtl, g_wtl);

    cudaStream_t s2 = g_pipe.s2;

    // fork: s2 joins the capture DAG off the default stream
    cudaEventRecord(g_pipe.evRoot, 0);
    cudaStreamWaitEvent(s2, g_pipe.evRoot, 0);

    // transpose (independent of RNN) on s2
    dim3 tgrid((VOCAB + 31) / 32, HID / 32);           // (313, 8)
    wd_transpose_split<<<tgrid, dim3(32, 8), 0, s2>>>(Wd);

    dim3 ggrid((VOCAB + GBN - 1) / GBN, (MTOT / NCH) / GBM);   // (79, 16)
    for (int c = 0; c < NCH; c++) {
        // RNN chunk c on default stream (serial chain)
        rnn_kernel<<<BATCH, 256, RNN_SMEM_ALLOC>>>(tokens, state, Wxh, Whh, bh,
                                                   hfin, c * TCH);
        cudaEventRecord(g_pipe.evR[c], 0);
        // GEMM chunk c on s2, gated on RNN chunk c
        cudaStreamWaitEvent(s2, g_pipe.evR[c], 0);
        gemm_mma<<<ggrid, 256, GSMEM, s2>>>(yh, yl, wth, wtl, bd, out,
                                            c * (MTOT / NCH));
    }

    // join: default stream waits for the GEMM stream
    cudaEventRecord(g_pipe.evDone, s2);
    cudaStreamWaitEvent(0, g_pipe.evDone, 0);
}

// round 12
// speedup vs baseline: 1.4996x; 1.0374x over previous
#include <cuda_runtime.h>
#include <cuda_bf16.h>
#include <cstdint>

// Problem constants
#define VOCAB 10000
#define HID   256
#define BATCH 32
#define SEQL  512
#define MTOT  (SEQL * BATCH)   // 16384
#define NCH   8                // RNN/GEMM pipeline chunks
#define TCH   (SEQL / NCH)     // 64 timesteps per chunk

typedef unsigned long long u64;

// ---------------- scratch ----------------
__device__ __nv_bfloat16 g_yh[(size_t)MTOT * HID];    // Y hi  [M, K]
__device__ __nv_bfloat16 g_yl[(size_t)MTOT * HID];    // Y lo  [M, K]
__device__ __nv_bfloat16 g_wth[(size_t)VOCAB * HID];  // Wd^T hi [N, K]
__device__ __nv_bfloat16 g_wtl[(size_t)VOCAB * HID];  // Wd^T lo [N, K]
__device__ float g_state[BATCH * HID];                // h carried between chunks

// ================= helpers =================
__device__ __forceinline__ uint32_t smem_u32(const void* p) {
    uint32_t a;
    asm("{ .reg .u64 t; cvta.to.shared.u64 t, %1; cvt.u32.u64 %0, t; }"
        : "=r"(a) : "l"(p));
    return a;
}
__device__ __forceinline__ void cpa16(uint32_t dst, const void* src, uint32_t sz) {
    asm volatile("cp.async.cg.shared.global [%0], [%1], 16, %2;"
                 :: "r"(dst), "l"(src), "r"(sz) : "memory");
}
__device__ __forceinline__ void ldm_x4(uint32_t* r, uint32_t addr) {
    asm volatile("ldmatrix.sync.aligned.m8n8.x4.shared.b16 {%0,%1,%2,%3}, [%4];"
                 : "=r"(r[0]), "=r"(r[1]), "=r"(r[2]), "=r"(r[3]) : "r"(addr));
}
__device__ __forceinline__ void mma_bf16(float* c, const uint32_t* a, const uint32_t* b) {
    asm volatile(
        "mma.sync.aligned.m16n8k16.row.col.f32.bf16.bf16.f32 "
        "{%0,%1,%2,%3}, {%4,%5,%6,%7}, {%8,%9}, {%0,%1,%2,%3};"
        : "+f"(c[0]), "+f"(c[1]), "+f"(c[2]), "+f"(c[3])
        : "r"(a[0]), "r"(a[1]), "r"(a[2]), "r"(a[3]), "r"(b[0]), "r"(b[1]));
}
__device__ __forceinline__ u64 packf2(float lo, float hi) {
    u64 d;
    asm("mov.b64 %0, {%1, %2};" : "=l"(d) : "f"(lo), "f"(hi));
    return d;
}
__device__ __forceinline__ void unpackf2(u64 d, float& lo, float& hi) {
    asm("mov.b64 {%0, %1}, %2;" : "=f"(lo), "=f"(hi) : "l"(d));
}
__device__ __forceinline__ u64 fma2(u64 a, u64 b, u64 c) {
    u64 d;
    asm("fma.rn.f32x2 %0, %1, %2, %3;" : "=l"(d) : "l"(a), "l"(b), "l"(c));
    return d;
}
// fast tanh: 1 - 2/(e^{2x}+1); saturates correctly at +-inf
__device__ __forceinline__ float fast_tanh(float x) {
    float z = __expf(2.0f * x);
    return 1.0f - __fdividef(2.0f, z + 1.0f);
}

// ---------------- Recurrence chunk kernel (t in [t0, t0+TCH)) ----
// 2-deep embedding prefetch: the Wxh row for t+2 is issued during step t,
// giving ~2 steps (~5us) of latency slack against loaded DRAM/L2.
#define KREG 128
#define KSH  (HID - KREG)
#define KSHQ (KSH / 4)
#define RNN_SMEM (KSHQ * HID * 16)               // 131072

__global__ void __launch_bounds__(256, 1)
rnn_kernel(const int* __restrict__ tokens, const float* __restrict__ state,
           const float* __restrict__ Wxh, const float* __restrict__ Whh,
           const float* __restrict__ bh, float* __restrict__ hfin, int t0)
{
    extern __shared__ float4 Wsh4[];                 // [KSHQ][HID] float4
    __shared__ __align__(16) float hbuf[2][HID];

    const int b = blockIdx.x;
    const int i = threadIdx.x;

    // Whh rows [0, KREG) for column i, packed as 64 f32x2 pairs
    u64 Wreg2[KREG / 2];
#pragma unroll
    for (int q = 0; q < KREG / 2; q++)
        Wreg2[q] = packf2(Whh[(2 * q) * HID + i], Whh[(2 * q + 1) * HID + i]);

    // Whh rows [KREG, 256) in shared as float4 per (kq, i)
    for (int kq = 0; kq < KSHQ; kq++) {
        float4 v;
        v.x = Whh[(KREG + 4 * kq + 0) * HID + i];
        v.y = Whh[(KREG + 4 * kq + 1) * HID + i];
        v.z = Whh[(KREG + 4 * kq + 2) * HID + i];
        v.w = Whh[(KREG + 4 * kq + 3) * HID + i];
        Wsh4[kq * HID + i] = v;
    }

    const float bias = bh[i];
    hbuf[0][i] = (t0 == 0) ? state[b * HID + i] : g_state[b * HID + i];
    __syncthreads();

    const int* toks = tokens + b * SEQL;
    float e0 = Wxh[toks[t0] * HID + i];
    float e1 = (t0 + 1 < SEQL) ? Wxh[toks[t0 + 1] * HID + i] : 0.f;
    int cur = 0;
    float hn = 0.f;

    const int tend = t0 + TCH;
    for (int t = t0; t < tend; t++) {
        // issue t+2 prefetch before the dot product
        float e2 = (t + 2 < SEQL) ? Wxh[toks[t + 2] * HID + i] : 0.f;

        u64 acc[4];
        acc[0] = packf2(e0 + bias, 0.f);
        acc[1] = 0ull; acc[2] = 0ull; acc[3] = 0ull;

        const ulonglong2* h22 = (const ulonglong2*)hbuf[cur];

#pragma unroll
        for (int q = 0; q < KREG / 4; q++) {
            ulonglong2 hv = h22[q];
            acc[0] = fma2(hv.x, Wreg2[2 * q],     acc[0]);
            acc[1] = fma2(hv.y, Wreg2[2 * q + 1], acc[1]);
        }
#pragma unroll
        for (int kq = 0; kq < KSHQ; kq++) {
            ulonglong2 hv = h22[KREG / 4 + kq];
            float4 wv = Wsh4[kq * HID + i];
            const u64* wp = (const u64*)&wv;
            acc[2] = fma2(hv.x, wp[0], acc[2]);
            acc[3] = fma2(hv.y, wp[1], acc[3]);
        }

        float s0, s1, s2, s3, s4, s5, s6, s7;
        unpackf2(acc[0], s0, s1);
        unpackf2(acc[1], s2, s3);
        unpackf2(acc[2], s4, s5);
        unpackf2(acc[3], s6, s7);
        float sum = ((s0 + s2) + (s1 + s3)) + ((s4 + s6) + (s5 + s7));

        hn = fast_tanh(sum);
        size_t oidx = ((size_t)t * BATCH + b) * HID + i;
        __nv_bfloat16 hh = __float2bfloat16(hn);
        g_yh[oidx] = hh;
        g_yl[oidx] = __float2bfloat16(hn - __bfloat162float(hh));
        hbuf[cur ^ 1][i] = hn;
        __syncthreads();
        cur ^= 1;
        e0 = e1;
        e1 = e2;
    }

    // carry state to next chunk / final output
    g_state[b * HID + i] = hn;
    if (tend == SEQL) hfin[b * HID + i] = hn;
}

// ---------------- Wd transpose + bf16 split: [K,N] f32 -> [N,K] bf16 hi/lo --
__global__ void __launch_bounds__(256)
wd_transpose_split(const float* __restrict__ Wd)
{
    __shared__ float tile[32][33];
    const int tx = threadIdx.x;          // 0..31
    const int ty = threadIdx.y;          // 0..7
    const int n0 = blockIdx.x * 32;
    const int k0 = blockIdx.y * 32;

#pragma unroll
    for (int r = 0; r < 4; r++) {
        int k = k0 + ty + r * 8;
        int n = n0 + tx;
        tile[ty + r * 8][tx] = (n < VOCAB) ? Wd[(size_t)k * VOCAB + n] : 0.f;
    }
    __syncthreads();

#pragma unroll
    for (int r = 0; r < 4; r++) {
        int n = n0 + ty + r * 8;
        int k = k0 + tx;
        if (n < VOCAB) {
            float v = tile[tx][ty + r * 8];
            __nv_bfloat16 hi = __float2bfloat16(v);
            g_wth[(size_t)n * HID + k] = hi;
            g_wtl[(size_t)n * HID + k] = __float2bfloat16(v - __bfloat162float(hi));
        }
    }
}

// ---------------- mma.sync GEMM (128x128, 2 CTA/SM) --------------
#define GBM 128
#define GBN 128
#define GBK 32
#define ROWB 80                            // bytes per smem row (32 bf16 + pad)
#define MATB (128 * ROWB)                  // 10240 B per matrix tile
#define STAGEB (4 * MATB)                  // Ah, Al, Bh, Bl
#define GSMEM (2 * STAGEB)                 // 81920 B

__global__ void __launch_bounds__(256, 2)
gemm_mma(const __nv_bfloat16* __restrict__ Yh, const __nv_bfloat16* __restrict__ Yl,
         const __nv_bfloat16* __restrict__ Bth, const __nv_bfloat16* __restrict__ Btl,
         const float* __restrict__ bd, float* __restrict__ C, int m_base)
{
    extern __shared__ __align__(16) char smraw[];
    const uint32_t base = smem_u32(smraw);

    const int tid  = threadIdx.x;
    const int lane = tid & 31;
    const int wid  = tid >> 5;
    const int wm   = wid & 1;              // 0..1
    const int wn   = wid >> 1;             // 0..3
    const int m0   = m_base + blockIdx.y * GBM;
    const int n0   = blockIdx.x * GBN;

    float acc[4][4][4];
#pragma unroll
    for (int i = 0; i < 4; i++)
#pragma unroll
        for (int j = 0; j < 4; j++)
#pragma unroll
            for (int q = 0; q < 4; q++)
                acc[i][j][q] = 0.f;

    auto load_stage = [&](int st, int kc) {
        const uint32_t sb = base + st * STAGEB;
        const int kel = kc * GBK;
#pragma unroll
        for (int j = 0; j < 2; j++) {
            int u = tid + j * 256;
            int r = u >> 2;
            int sg = u & 3;
            uint32_t off = (uint32_t)r * ROWB + sg * 16;
            cpa16(sb + 0 * MATB + off, Yh + (size_t)(m0 + r) * HID + kel + sg * 8, 16);
            cpa16(sb + 1 * MATB + off, Yl + (size_t)(m0 + r) * HID + kel + sg * 8, 16);
            int nr = n0 + r;
            uint32_t ok = (nr < VOCAB) ? 16u : 0u;
            size_t br = (nr < VOCAB) ? (size_t)nr : 0;
            cpa16(sb + 2 * MATB + off, Bth + br * HID + kel + sg * 8, ok);
            cpa16(sb + 3 * MATB + off, Btl + br * HID + kel + sg * 8, ok);
        }
        asm volatile("cp.async.commit_group;" ::: "memory");
    };

    load_stage(0, 0);

    const int NKC = HID / GBK;             // 8 chunks
    for (int kc = 0; kc < NKC; kc++) {
        if (kc + 1 < NKC) {
            load_stage((kc + 1) & 1, kc + 1);
            asm volatile("cp.async.wait_group 1;" ::: "memory");
        } else {
            asm volatile("cp.async.wait_group 0;" ::: "memory");
        }
        __syncthreads();

        const uint32_t sb = base + (kc & 1) * STAGEB;
        const uint32_t Ah = sb, Al = sb + MATB, Bh = sb + 2 * MATB, Bl = sb + 3 * MATB;

#pragma unroll
        for (int ks = 0; ks < 2; ks++) {
            const int k0 = ks * 16;
            uint32_t bh[2][4], bl[2][4];
#pragma unroll
            for (int h = 0; h < 2; h++) {
                int row = wn * 32 + h * 16 + ((lane >> 4) & 1) * 8 + (lane & 7);
                int col = k0 + ((lane >> 3) & 1) * 8;
                uint32_t off = (uint32_t)row * ROWB + col * 2;
                ldm_x4(bh[h], Bh + off);
                ldm_x4(bl[h], Bl + off);
            }
#pragma unroll
            for (int mi = 0; mi < 4; mi++) {
                int rowA = wm * 64 + mi * 16 + (lane & 15);
                int colA = k0 + (lane >> 4) * 8;
                uint32_t offA = (uint32_t)rowA * ROWB + colA * 2;
                uint32_t ah[4], al[4];
                ldm_x4(ah, Ah + offA);
                ldm_x4(al, Al + offA);
#pragma unroll
                for (int ni = 0; ni < 4; ni++) {
                    const uint32_t* ph = &bh[ni >> 1][(ni & 1) * 2];
                    const uint32_t* pl = &bl[ni >> 1][(ni & 1) * 2];
                    mma_bf16(acc[mi][ni], ah, ph);   // Ah * Bh
                    mma_bf16(acc[mi][ni], ah, pl);   // Ah * Bl
                    mma_bf16(acc[mi][ni], al, ph);   // Al * Bh
                }
            }
        }
        __syncthreads();
    }

    // ---- epilogue: bias + store ----
    const int g  = lane >> 2;
    const int tq = lane & 3;
#pragma unroll
    for (int mi = 0; mi < 4; mi++) {
        int r0 = m0 + wm * 64 + mi * 16 + g;
#pragma unroll
        for (int ni = 0; ni < 4; ni++) {
            int col = n0 + wn * 32 + ni * 8 + tq * 2;
            if (col < VOCAB) {
                float b0 = bd[col], b1 = bd[col + 1];
                float2 v0 = { acc[mi][ni][0] + b0, acc[mi][ni][1] + b1 };
                float2 v1 = { acc[mi][ni][2] + b0, acc[mi][ni][3] + b1 };
                *(float2*)(C + (size_t)r0 * VOCAB + col) = v0;
                *(float2*)(C + (size_t)(r0 + 8) * VOCAB + col) = v1;
            }
        }
    }
}

// ---------------- stream/event plumbing (created pre-main, no device allocs
// inside kernel_launch; events are timing-disabled for graph capture) -------
struct PipeResources {
    cudaStream_t s2;
    cudaEvent_t evRoot, evR[NCH], evDone;
    PipeResources() {
        cudaStreamCreateWithFlags(&s2, cudaStreamNonBlocking);
        cudaEventCreateWithFlags(&evRoot, cudaEventDisableTiming);
        for (int c = 0; c < NCH; c++)
            cudaEventCreateWithFlags(&evR[c], cudaEventDisableTiming);
        cudaEventCreateWithFlags(&evDone, cudaEventDisableTiming);
    }
};
static PipeResources g_pipe;

// ---------------- launcher: fork-join RNN/GEMM pipeline ----------------
extern "C" void kernel_launch(void* const* d_in, const int* in_sizes, int n_in,
                              void* d_out, int out_size)
{
    const int*   tokens = (const int*)  d_in[0];  // [32, 512] int32
    const float* state  = (const float*)d_in[1];  // [32, 256]
    const float* Wxh    = (const float*)d_in[2];  // [10000, 256]
    const float* Whh    = (const float*)d_in[3];  // [256, 256]
    const float* bh     = (const float*)d_in[4];  // [256]
    const float* Wd     = (const float*)d_in[5];  // [256, 10000]
    const float* bd     = (const float*)d_in[6];  // [10000]

    float* out  = (float*)d_out;                       // [16384, 10000]
    float* hfin = out + (size_t)MTOT * VOCAB;          // [32, 256]

    cudaFuncSetAttribute(rnn_kernel,
                         cudaFuncAttributeMaxDynamicSharedMemorySize, RNN_SMEM);
    cudaFuncSetAttribute(gemm_mma,
                         cudaFuncAttributeMaxDynamicSharedMemorySize, GSMEM);

    __nv_bfloat16 *yh, *yl, *wth, *wtl;
    cudaGetSymbolAddress((void**)&yh,  g_yh);
    cudaGetSymbolAddress((void**)&yl,  g_yl);
    cudaGetSymbolAddress((void**)&wth, g_wth);
    cudaGetSymbolAddress((void**)&wtl, g_wtl);

    cudaStream_t s2 = g_pipe.s2;

    // fork: s2 joins the capture DAG off the default stream
    cudaEventRecord(g_pipe.evRoot, 0);
    cudaStreamWaitEvent(s2, g_pipe.evRoot, 0);

    // transpose (independent of RNN) on s2
    dim3 tgrid((VOCAB + 31) / 32, HID / 32);           // (313, 8)
    wd_transpose_split<<<tgrid, dim3(32, 8), 0, s2>>>(Wd);

    dim3 ggrid((VOCAB + GBN - 1) / GBN, (MTOT / NCH) / GBM);   // (79, 16)
    for (int c = 0; c < NCH; c++) {
        // RNN chunk c on default stream (serial chain)
        rnn_kernel<<<BATCH, 256, RNN_SMEM>>>(tokens, state, Wxh, Whh, bh,
                                             hfin, c * TCH);
        cudaEventRecord(g_pipe.evR[c], 0);
        // GEMM chunk c on s2, gated on RNN chunk c
        cudaStreamWaitEvent(s2, g_pipe.evR[c], 0);
        gemm_mma<<<ggrid, 256, GSMEM, s2>>>(yh, yl, wth, wtl, bd, out,
                                            c * (MTOT / NCH));
    }

    // join: default stream waits for the GEMM stream
    cudaEventRecord(g_pipe.evDone, s2);
    cudaStreamWaitEvent(0, g_pipe.evDone, 0);
}

// round 13
// speedup vs baseline: 1.8769x; 1.2516x over previous
#include <cuda_runtime.h>
#include <cuda_bf16.h>
#include <cuda_fp16.h>
#include <cstdint>

// Problem constants
#define VOCAB 10000
#define HID   256
#define BATCH 32
#define SEQL  512
#define MTOT  (SEQL * BATCH)   // 16384
#define NCH   8                // RNN/GEMM pipeline chunks
#define TCH   (SEQL / NCH)     // 64 timesteps per chunk

typedef unsigned long long u64;

// ---------------- scratch (fp16 split operands) ----------------
__device__ __half g_yh[(size_t)MTOT * HID];    // Y hi  [M, K] fp16
__device__ __half g_yl[(size_t)MTOT * HID];    // Y lo  [M, K] fp16 (residual)
__device__ __half g_wt[(size_t)VOCAB * HID];   // Wd^T  [N, K] fp16 (single)
__device__ float g_state[BATCH * HID];         // h carried between chunks

// ================= helpers =================
__device__ __forceinline__ uint32_t smem_u32(const void* p) {
    uint32_t a;
    asm("{ .reg .u64 t; cvta.to.shared.u64 t, %1; cvt.u32.u64 %0, t; }"
        : "=r"(a) : "l"(p));
    return a;
}
__device__ __forceinline__ void cpa16(uint32_t dst, const void* src, uint32_t sz) {
    asm volatile("cp.async.cg.shared.global [%0], [%1], 16, %2;"
                 :: "r"(dst), "l"(src), "r"(sz) : "memory");
}
__device__ __forceinline__ void ldm_x4(uint32_t* r, uint32_t addr) {
    asm volatile("ldmatrix.sync.aligned.m8n8.x4.shared.b16 {%0,%1,%2,%3}, [%4];"
                 : "=r"(r[0]), "=r"(r[1]), "=r"(r[2]), "=r"(r[3]) : "r"(addr));
}
__device__ __forceinline__ void mma_fp16(float* c, const uint32_t* a, const uint32_t* b) {
    asm volatile(
        "mma.sync.aligned.m16n8k16.row.col.f32.f16.f16.f32 "
        "{%0,%1,%2,%3}, {%4,%5,%6,%7}, {%8,%9}, {%0,%1,%2,%3};"
        : "+f"(c[0]), "+f"(c[1]), "+f"(c[2]), "+f"(c[3])
        : "r"(a[0]), "r"(a[1]), "r"(a[2]), "r"(a[3]), "r"(b[0]), "r"(b[1]));
}
__device__ __forceinline__ u64 packf2(float lo, float hi) {
    u64 d;
    asm("mov.b64 %0, {%1, %2};" : "=l"(d) : "f"(lo), "f"(hi));
    return d;
}
__device__ __forceinline__ void unpackf2(u64 d, float& lo, float& hi) {
    asm("mov.b64 {%0, %1}, %2;" : "=f"(lo), "=f"(hi) : "l"(d));
}
__device__ __forceinline__ u64 fma2(u64 a, u64 b, u64 c) {
    u64 d;
    asm("fma.rn.f32x2 %0, %1, %2, %3;" : "=l"(d) : "l"(a), "l"(b), "l"(c));
    return d;
}
// fast tanh: 1 - 2/(e^{2x}+1); saturates correctly at +-inf
__device__ __forceinline__ float fast_tanh(float x) {
    float z = __expf(2.0f * x);
    return 1.0f - __fdividef(2.0f, z + 1.0f);
}

// ---------------- Recurrence chunk kernel (t in [t0, t0+TCH)) ----
// 2-deep embedding prefetch (R12). Outputs now fp16 hi/lo split.
#define KREG 128
#define KSH  (HID - KREG)
#define KSHQ (KSH / 4)
#define RNN_SMEM (KSHQ * HID * 16)               // 131072

__global__ void __launch_bounds__(256, 1)
rnn_kernel(const int* __restrict__ tokens, const float* __restrict__ state,
           const float* __restrict__ Wxh, const float* __restrict__ Whh,
           const float* __restrict__ bh, float* __restrict__ hfin, int t0)
{
    extern __shared__ float4 Wsh4[];                 // [KSHQ][HID] float4
    __shared__ __align__(16) float hbuf[2][HID];

    const int b = blockIdx.x;
    const int i = threadIdx.x;

    // Whh rows [0, KREG) for column i, packed as 64 f32x2 pairs
    u64 Wreg2[KREG / 2];
#pragma unroll
    for (int q = 0; q < KREG / 2; q++)
        Wreg2[q] = packf2(Whh[(2 * q) * HID + i], Whh[(2 * q + 1) * HID + i]);

    // Whh rows [KREG, 256) in shared as float4 per (kq, i)
    for (int kq = 0; kq < KSHQ; kq++) {
        float4 v;
        v.x = Whh[(KREG + 4 * kq + 0) * HID + i];
        v.y = Whh[(KREG + 4 * kq + 1) * HID + i];
        v.z = Whh[(KREG + 4 * kq + 2) * HID + i];
        v.w = Whh[(KREG + 4 * kq + 3) * HID + i];
        Wsh4[kq * HID + i] = v;
    }

    const float bias = bh[i];
    hbuf[0][i] = (t0 == 0) ? state[b * HID + i] : g_state[b * HID + i];
    __syncthreads();

    const int* toks = tokens + b * SEQL;
    float e0 = Wxh[toks[t0] * HID + i];
    float e1 = (t0 + 1 < SEQL) ? Wxh[toks[t0 + 1] * HID + i] : 0.f;
    int cur = 0;
    float hn = 0.f;

    const int tend = t0 + TCH;
    for (int t = t0; t < tend; t++) {
        // issue t+2 prefetch before the dot product
        float e2 = (t + 2 < SEQL) ? Wxh[toks[t + 2] * HID + i] : 0.f;

        u64 acc[4];
        acc[0] = packf2(e0 + bias, 0.f);
        acc[1] = 0ull; acc[2] = 0ull; acc[3] = 0ull;

        const ulonglong2* h22 = (const ulonglong2*)hbuf[cur];

#pragma unroll
        for (int q = 0; q < KREG / 4; q++) {
            ulonglong2 hv = h22[q];
            acc[0] = fma2(hv.x, Wreg2[2 * q],     acc[0]);
            acc[1] = fma2(hv.y, Wreg2[2 * q + 1], acc[1]);
        }
#pragma unroll
        for (int kq = 0; kq < KSHQ; kq++) {
            ulonglong2 hv = h22[KREG / 4 + kq];
            float4 wv = Wsh4[kq * HID + i];
            const u64* wp = (const u64*)&wv;
            acc[2] = fma2(hv.x, wp[0], acc[2]);
            acc[3] = fma2(hv.y, wp[1], acc[3]);
        }

        float s0, s1, s2, s3, s4, s5, s6, s7;
        unpackf2(acc[0], s0, s1);
        unpackf2(acc[1], s2, s3);
        unpackf2(acc[2], s4, s5);
        unpackf2(acc[3], s6, s7);
        float sum = ((s0 + s2) + (s1 + s3)) + ((s4 + s6) + (s5 + s7));

        hn = fast_tanh(sum);
        size_t oidx = ((size_t)t * BATCH + b) * HID + i;
        __half hh = __float2half(hn);
        g_yh[oidx] = hh;
        g_yl[oidx] = __float2half(hn - __half2float(hh));
        hbuf[cur ^ 1][i] = hn;
        __syncthreads();
        cur ^= 1;
        e0 = e1;
        e1 = e2;
    }

    // carry state to next chunk / final output
    g_state[b * HID + i] = hn;
    if (tend == SEQL) hfin[b * HID + i] = hn;
}

// ---------------- Wd transpose + fp16 convert: [K,N] f32 -> [N,K] fp16 -----
__global__ void __launch_bounds__(256)
wd_transpose_split(const float* __restrict__ Wd)
{
    __shared__ float tile[32][33];
    const int tx = threadIdx.x;          // 0..31
    const int ty = threadIdx.y;          // 0..7
    const int n0 = blockIdx.x * 32;
    const int k0 = blockIdx.y * 32;

#pragma unroll
    for (int r = 0; r < 4; r++) {
        int k = k0 + ty + r * 8;
        int n = n0 + tx;
        tile[ty + r * 8][tx] = (n < VOCAB) ? Wd[(size_t)k * VOCAB + n] : 0.f;
    }
    __syncthreads();

#pragma unroll
    for (int r = 0; r < 4; r++) {
        int n = n0 + ty + r * 8;
        int k = k0 + tx;
        if (n < VOCAB)
            g_wt[(size_t)n * HID + k] = __float2half(tile[tx][ty + r * 8]);
    }
}

// ---------------- mma.sync GEMM: C = (Yh+Yl) @ Wt^T + bd (fp16, 2-pass) -----
// 128x128 CTA tile, 8 warps (2x4), 64x32 per warp, GBK=32, 2-stage cp.async.
// Stage holds 3 tiles: Ah, Al (fp16 split of Y) and B (single fp16 Wd^T).
#define GBM 128
#define GBN 128
#define GBK 32
#define ROWB 80                            // bytes per smem row (32 fp16 + pad)
#define MATB (128 * ROWB)                  // 10240 B per matrix tile
#define STAGEB (3 * MATB)                  // Ah, Al, B
#define GSMEM (2 * STAGEB)                 // 61440 B

__global__ void __launch_bounds__(256, 2)
gemm_mma(const __half* __restrict__ Yh, const __half* __restrict__ Yl,
         const __half* __restrict__ Bt, const float* __restrict__ bd,
         float* __restrict__ C, int m_base)
{
    extern __shared__ __align__(16) char smraw[];
    const uint32_t base = smem_u32(smraw);

    const int tid  = threadIdx.x;
    const int lane = tid & 31;
    const int wid  = tid >> 5;
    const int wm   = wid & 1;              // 0..1
    const int wn   = wid >> 1;             // 0..3
    const int m0   = m_base + blockIdx.y * GBM;
    const int n0   = blockIdx.x * GBN;

    float acc[4][4][4];
#pragma unroll
    for (int i = 0; i < 4; i++)
#pragma unroll
        for (int j = 0; j < 4; j++)
#pragma unroll
            for (int q = 0; q < 4; q++)
                acc[i][j][q] = 0.f;

    auto load_stage = [&](int st, int kc) {
        const uint32_t sb = base + st * STAGEB;
        const int kel = kc * GBK;
#pragma unroll
        for (int j = 0; j < 2; j++) {
            int u = tid + j * 256;
            int r = u >> 2;
            int sg = u & 3;
            uint32_t off = (uint32_t)r * ROWB + sg * 16;
            cpa16(sb + 0 * MATB + off, Yh + (size_t)(m0 + r) * HID + kel + sg * 8, 16);
            cpa16(sb + 1 * MATB + off, Yl + (size_t)(m0 + r) * HID + kel + sg * 8, 16);
            int nr = n0 + r;
            uint32_t ok = (nr < VOCAB) ? 16u : 0u;
            size_t br = (nr < VOCAB) ? (size_t)nr : 0;
            cpa16(sb + 2 * MATB + off, Bt + br * HID + kel + sg * 8, ok);
        }
        asm volatile("cp.async.commit_group;" ::: "memory");
    };

    load_stage(0, 0);

    const int NKC = HID / GBK;             // 8 chunks
    for (int kc = 0; kc < NKC; kc++) {
        if (kc + 1 < NKC) {
            load_stage((kc + 1) & 1, kc + 1);
            asm volatile("cp.async.wait_group 1;" ::: "memory");
        } else {
            asm volatile("cp.async.wait_group 0;" ::: "memory");
        }
        __syncthreads();

        const uint32_t sb = base + (kc & 1) * STAGEB;
        const uint32_t Ah = sb, Al = sb + MATB, Bm = sb + 2 * MATB;

#pragma unroll
        for (int ks = 0; ks < 2; ks++) {
            const int k0 = ks * 16;
            // B fragments: 2 x ldm.x4 (non-trans) -> 32 cols x 16 k
            uint32_t bf[2][4];
#pragma unroll
            for (int h = 0; h < 2; h++) {
                int row = wn * 32 + h * 16 + ((lane >> 4) & 1) * 8 + (lane & 7);
                int col = k0 + ((lane >> 3) & 1) * 8;
                uint32_t off = (uint32_t)row * ROWB + col * 2;
                ldm_x4(bf[h], Bm + off);
            }
#pragma unroll
            for (int mi = 0; mi < 4; mi++) {
                int rowA = wm * 64 + mi * 16 + (lane & 15);
                int colA = k0 + (lane >> 4) * 8;
                uint32_t offA = (uint32_t)rowA * ROWB + colA * 2;
                uint32_t ah[4], al[4];
                ldm_x4(ah, Ah + offA);
                ldm_x4(al, Al + offA);
#pragma unroll
                for (int ni = 0; ni < 4; ni++) {
                    const uint32_t* pb = &bf[ni >> 1][(ni & 1) * 2];
                    mma_fp16(acc[mi][ni], ah, pb);   // Ah * B
                    mma_fp16(acc[mi][ni], al, pb);   // Al * B
                }
            }
        }
        __syncthreads();
    }

    // ---- epilogue: bias + store ----
    const int g  = lane >> 2;
    const int tq = lane & 3;
#pragma unroll
    for (int mi = 0; mi < 4; mi++) {
        int r0 = m0 + wm * 64 + mi * 16 + g;
#pragma unroll
        for (int ni = 0; ni < 4; ni++) {
            int col = n0 + wn * 32 + ni * 8 + tq * 2;
            if (col < VOCAB) {
                float b0 = bd[col], b1 = bd[col + 1];
                float2 v0 = { acc[mi][ni][0] + b0, acc[mi][ni][1] + b1 };
                float2 v1 = { acc[mi][ni][2] + b0, acc[mi][ni][3] + b1 };
                *(float2*)(C + (size_t)r0 * VOCAB + col) = v0;
                *(float2*)(C + (size_t)(r0 + 8) * VOCAB + col) = v1;
            }
        }
    }
}

// ---------------- stream/event plumbing (created pre-main, no device allocs
// inside kernel_launch; events are timing-disabled for graph capture) -------
struct PipeResources {
    cudaStream_t s2;
    cudaEvent_t evRoot, evR[NCH], evDone;
    PipeResources() {
        cudaStreamCreateWithFlags(&s2, cudaStreamNonBlocking);
        cudaEventCreateWithFlags(&evRoot, cudaEventDisableTiming);
        for (int c = 0; c < NCH; c++)
            cudaEventCreateWithFlags(&evR[c], cudaEventDisableTiming);
        cudaEventCreateWithFlags(&evDone, cudaEventDisableTiming);
    }
};
static PipeResources g_pipe;

// ---------------- launcher: fork-join RNN/GEMM pipeline ----------------
extern "C" void kernel_launch(void* const* d_in, const int* in_sizes, int n_in,
                              void* d_out, int out_size)
{
    const int*   tokens = (const int*)  d_in[0];  // [32, 512] int32
    const float* state  = (const float*)d_in[1];  // [32, 256]
    const float* Wxh    = (const float*)d_in[2];  // [10000, 256]
    const float* Whh    = (const float*)d_in[3];  // [256, 256]
    const float* bh     = (const float*)d_in[4];  // [256]
    const float* Wd     = (const float*)d_in[5];  // [256, 10000]
    const float* bd     = (const float*)d_in[6];  // [10000]

    float* out  = (float*)d_out;                       // [16384, 10000]
    float* hfin = out + (size_t)MTOT * VOCAB;          // [32, 256]

    cudaFuncSetAttribute(rnn_kernel,
                         cudaFuncAttributeMaxDynamicSharedMemorySize, RNN_SMEM);
    cudaFuncSetAttribute(gemm_mma,
                         cudaFuncAttributeMaxDynamicSharedMemorySize, GSMEM);

    __half *yh, *yl, *wt;
    cudaGetSymbolAddress((void**)&yh, g_yh);
    cudaGetSymbolAddress((void**)&yl, g_yl);
    cudaGetSymbolAddress((void**)&wt, g_wt);

    cudaStream_t s2 = g_pipe.s2;

    // fork: s2 joins the capture DAG off the default stream
    cudaEventRecord(g_pipe.evRoot, 0);
    cudaStreamWaitEvent(s2, g_pipe.evRoot, 0);

    // transpose (independent of RNN) on s2
    dim3 tgrid((VOCAB + 31) / 32, HID / 32);           // (313, 8)
    wd_transpose_split<<<tgrid, dim3(32, 8), 0, s2>>>(Wd);

    dim3 ggrid((VOCAB + GBN - 1) / GBN, (MTOT / NCH) / GBM);   // (79, 16)
    for (int c = 0; c < NCH; c++) {
        // RNN chunk c on default stream (serial chain)
        rnn_kernel<<<BATCH, 256, RNN_SMEM>>>(tokens, state, Wxh, Whh, bh,
                                             hfin, c * TCH);
        cudaEventRecord(g_pipe.evR[c], 0);
        // GEMM chunk c on s2, gated on RNN chunk c
        cudaStreamWaitEvent(s2, g_pipe.evR[c], 0);
        gemm_mma<<<ggrid, 256, GSMEM, s2>>>(yh, yl, wt, bd, out,
                                            c * (MTOT / NCH));
    }

    // join: default stream waits for the GEMM stream
    cudaEventRecord(g_pipe.evDone, s2);
    cudaStreamWaitEvent(0, g_pipe.evDone, 0);
}